// round 10
// baseline (speedup 1.0000x reference)
#include <cuda_runtime.h>
#include <cuda_bf16.h>
#include <math.h>
#include <cstdint>

// ---------------------------------------------------------------------------
// SSMXLSTMFusion: D=512, S=3, BATCH=256, H=8, HD=64
// Round 10: pre-split all GEMM operands to bf16 hi/lo in GMEM (split ONCE),
// GEMM mainloop is pure cp.async -> ldmatrix -> mma (no cvt math), 3-stage
// circular buffer, 1 sync/chunk. Taylor chain 2x8 terms (A^1..A^8, KT=16).
// ---------------------------------------------------------------------------

#define DD    512
#define BB    256
#define SS    3
typedef __nv_bfloat16 bf16;

// ------------------------- fp32 scratch ------------------------------------
__device__ float g_h1   [BB*DD];
__device__ float g_delta[BB];
__device__ float g_bx   [BB*DD];
__device__ float g_U    [BB*8*DD];
__device__ float g_gA   [SS*BB*4*DD];
__device__ float g_gB   [SS*BB*4*DD];
__device__ float g_kvp  [2*SS*BB*2*DD];
__device__ float g_qp   [2*BB*DD];
__device__ float g_part [10*BB*DD];
__device__ float g_pvec [DD];

// ------------------------- bf16 hi/lo planes --------------------------------
__device__ bf16 g_xh[BB*DD],          g_xl[BB*DD];
__device__ bf16 g_hph[BB*DD],         g_hpl[BB*DD];        // h_prev
__device__ bf16 g_lhh[SS*BB*DD],      g_lhl[SS*BB*DD];     // lstm_h
__device__ bf16 g_w1h[DD*DD],         g_w1l[DD*DD];        // dn_w1
__device__ bf16 g_bmh[DD*DD],         g_bml[DD*DD];        // Bm
__device__ bf16 g_wihh[SS*4*DD*DD],   g_wihl[SS*4*DD*DD];
__device__ bf16 g_whhh[SS*4*DD*DD],   g_whhl[SS*4*DD*DD];
__device__ bf16 g_aiwh[3*DD*DD],      g_aiwl[3*DD*DD];     // attn_in_w
__device__ bf16 g_pwh[DD*5*DD],       g_pwl[DD*5*DD];      // proj_w
__device__ bf16 g_wpowh[8*DD*DD],     g_wpowl[8*DD*DD];    // A^1..A^8
__device__ bf16 g_ath[DD*DD],         g_atl[DD*DD];        // A^T
__device__ bf16 g_a2th[DD*DD],        g_a2tl[DD*DD];
__device__ bf16 g_a4th[DD*DD],        g_a4tl[DD*DD];
__device__ bf16 g_aoth[DD*DD],        g_aotl[DD*DD];       // attn_out_w^T
__device__ bf16 g_mh[DD*DD],          g_ml[DD*DD];         // M
__device__ bf16 g_th[BB*DD],          g_tl[BB*DD];         // chain T
__device__ bf16 g_hsh[BB*DD],         g_hsl[BB*DD];        // h_ssm
__device__ bf16 g_hnh[SS*BB*DD],      g_hnl[SS*BB*DD];     // h_new
__device__ bf16 g_cxh[BB*DD],         g_cxl[BB*DD];        // ctx

// ========================= descriptors ======================================
struct GTask {
    const bf16 *Xhi, *Xlo, *Whi, *Wlo, *Wn2hi, *Wn2lo;
    const float* bias;
    float *C, *Cn2;
    bf16 *Chi, *Clo, *Cthi, *Ctlo;
    int ldX, ldW, ldC, ldCn2, ldCt;
    int K, kofs, nsplit, mtiles, blocks;
};
struct GTaskSet { GTask t[12]; int ntasks; };

struct STask { const float* src; bf16 *hi, *lo; int blocks; };
struct STaskSet { STask t[12]; int ntasks; };

#define NOSPLIT (1<<30)

// ========================= smem layout ======================================
#define RSB     80
#define OFF_AHI 0
#define OFF_ALO 10240
#define OFF_BHI 20480
#define OFF_BLO 25600
#define STAGE   30720
#define SMEM_SZ (3*STAGE)      // 92160 bytes

__device__ __forceinline__ uint32_t smem_to_u32(const void* p) {
    uint32_t a;
    asm("{ .reg .u64 t; cvta.to.shared.u64 t, %1; cvt.u32.u64 %0, t; }"
        : "=r"(a) : "l"(p));
    return a;
}

__device__ __forceinline__ uint32_t pk2(bf16 a, bf16 b) {
    uint16_t ua = *(uint16_t*)&a, ub = *(uint16_t*)&b;
    return (uint32_t)ua | ((uint32_t)ub << 16);
}

__device__ __forceinline__ void split8(float4 u, float4 v, uint4& hi, uint4& lo)
{
    float f[8] = {u.x,u.y,u.z,u.w,v.x,v.y,v.z,v.w};
    uint32_t h[4], l[4];
    #pragma unroll
    for (int i = 0; i < 4; i++) {
        bf16 b0 = __float2bfloat16_rn(f[2*i]);
        bf16 b1 = __float2bfloat16_rn(f[2*i+1]);
        bf16 r0 = __float2bfloat16_rn(f[2*i]   - __bfloat162float(b0));
        bf16 r1 = __float2bfloat16_rn(f[2*i+1] - __bfloat162float(b1));
        h[i] = pk2(b0, b1);
        l[i] = pk2(r0, r1);
    }
    hi = make_uint4(h[0], h[1], h[2], h[3]);
    lo = make_uint4(l[0], l[1], l[2], l[3]);
}

__device__ __forceinline__ void ldm_x4(uint32_t* r, uint32_t addr) {
    asm volatile("ldmatrix.sync.aligned.m8n8.x4.shared.b16 {%0,%1,%2,%3}, [%4];"
        : "=r"(r[0]), "=r"(r[1]), "=r"(r[2]), "=r"(r[3]) : "r"(addr));
}

__device__ __forceinline__ void mma_bf16(float* c, const uint32_t* a, const uint32_t* b)
{
    asm volatile(
        "mma.sync.aligned.m16n8k16.row.col.f32.bf16.bf16.f32 "
        "{%0,%1,%2,%3}, {%4,%5,%6,%7}, {%8,%9}, {%0,%1,%2,%3};"
        : "+f"(c[0]), "+f"(c[1]), "+f"(c[2]), "+f"(c[3])
        : "r"(a[0]), "r"(a[1]), "r"(a[2]), "r"(a[3]), "r"(b[0]), "r"(b[1]));
}

#define CP16(saddr, gaddr) \
    asm volatile("cp.async.cg.shared.global [%0], [%1], 16;" \
        :: "r"(saddr), "l"(gaddr) : "memory")

// issue one 32-K chunk (A:128 rows hi+lo, B:64 rows hi+lo) via cp.async
__device__ __forceinline__ void issue_chunk(const GTask& T, uint32_t smb,
    int m0, int n0, int tid, int k0, int stage)
{
    const uint32_t sb = smb + (uint32_t)(stage * STAGE);
    #pragma unroll
    for (int j = 0; j < 4; j++) {
        int o  = tid + j*256;
        int pl = o >> 9;
        int r  = (o >> 2) & 127;
        int s  = o & 3;
        const bf16* g = (pl ? T.Xlo : T.Xhi) + (long)(m0 + r) * T.ldX + k0 + s*8;
        uint32_t sa = sb + (uint32_t)(pl*10240 + r*80 + s*16);
        CP16(sa, g);
    }
    #pragma unroll
    for (int j = 0; j < 2; j++) {
        int o  = tid + j*256;
        int pl = o >> 8;
        int r  = (o >> 2) & 63;
        int s  = o & 3;
        int ng = n0 + r;
        const bf16* w;
        if (ng >= T.nsplit)
            w = (pl ? T.Wn2lo : T.Wn2hi) + (long)(ng - T.nsplit) * T.ldW;
        else
            w = (pl ? T.Wlo : T.Whi) + (long)ng * T.ldW;
        uint32_t sa = sb + (uint32_t)(20480 + pl*5120 + r*80 + s*16);
        CP16(sa, w + k0 + s*8);
    }
    asm volatile("cp.async.commit_group;" ::: "memory");
}

// ========================= GEMM kernel ======================================
// 128(M) x 64(N) tile, 256 threads (warps 4m x 2n, warp tile 32x32),
// K chunks of 32, 3-stage cp.async pipeline, 1 sync per chunk. 2 CTAs/SM.
__global__ void __launch_bounds__(256, 2)
gemm_mma(GTaskSet ts)
{
    extern __shared__ char smem[];

    int b = blockIdx.x, ti = 0;
    while (b >= ts.t[ti].blocks) { b -= ts.t[ti].blocks; ti++; }
    const GTask T = ts.t[ti];
    const int m0 = (b % T.mtiles) * 128;
    const int n0 = (b / T.mtiles) * 64;

    const int tid = threadIdx.x;
    const int lid = tid & 31;
    const int wid = tid >> 5;
    const int m_base = (wid & 3) * 32;
    const int n_base = (wid >> 2) * 32;
    const int gid = lid >> 2;
    const int tig = lid & 3;
    const int g  = lid >> 3;
    const int ig = lid & 7;

    const uint32_t smb = smem_to_u32(smem);
    const uint32_t a_ad = smb + (uint32_t)((m_base + (g&1)*8 + ig) * RSB + (g>>1)*16);
    const uint32_t b_ad = smb + (uint32_t)((n_base + (g>>1)*8 + ig) * RSB + (g&1)*16);

    float acc[2][4][4];
    #pragma unroll
    for (int i = 0; i < 2; i++)
        #pragma unroll
        for (int j = 0; j < 4; j++)
            #pragma unroll
            for (int k = 0; k < 4; k++) acc[i][j][k] = 0.0f;

    const int nc = T.K >> 5;

    issue_chunk(T, smb, m0, n0, tid, T.kofs, 0);
    if (nc > 1) issue_chunk(T, smb, m0, n0, tid, T.kofs + 32, 1);

    for (int c = 0; c < nc; c++) {
        if (c + 1 < nc)
            asm volatile("cp.async.wait_group 1;" ::: "memory");
        else
            asm volatile("cp.async.wait_group 0;" ::: "memory");
        __syncthreads();

        if (c + 2 < nc)
            issue_chunk(T, smb, m0, n0, tid, T.kofs + (c+2)*32, (c+2)%3);

        const uint32_t sb = (uint32_t)((c % 3) * STAGE);
        #pragma unroll
        for (int ks = 0; ks < 2; ks++) {
            const uint32_t kb = sb + ks * 32;
            uint32_t ahi[2][4], alo[2][4], bhi[4][2], blo[4][2];
            #pragma unroll
            for (int mt = 0; mt < 2; mt++) {
                ldm_x4(ahi[mt], a_ad + OFF_AHI + mt*16*RSB + kb);
                ldm_x4(alo[mt], a_ad + OFF_ALO + mt*16*RSB + kb);
            }
            #pragma unroll
            for (int np = 0; np < 2; np++) {
                uint32_t r[4];
                ldm_x4(r, b_ad + OFF_BHI + np*16*RSB + kb);
                bhi[2*np][0] = r[0]; bhi[2*np][1] = r[1];
                bhi[2*np+1][0] = r[2]; bhi[2*np+1][1] = r[3];
                ldm_x4(r, b_ad + OFF_BLO + np*16*RSB + kb);
                blo[2*np][0] = r[0]; blo[2*np][1] = r[1];
                blo[2*np+1][0] = r[2]; blo[2*np+1][1] = r[3];
            }
            #pragma unroll
            for (int mt = 0; mt < 2; mt++)
                #pragma unroll
                for (int nt = 0; nt < 4; nt++) {
                    mma_bf16(acc[mt][nt], ahi[mt], bhi[nt]);
                    mma_bf16(acc[mt][nt], ahi[mt], blo[nt]);
                    mma_bf16(acc[mt][nt], alo[mt], bhi[nt]);
                }
        }
        __syncthreads();
    }

    // ---- epilogue ----
    #pragma unroll
    for (int mt = 0; mt < 2; mt++) {
        #pragma unroll
        for (int nt = 0; nt < 4; nt++) {
            int n = n0 + n_base + nt*8 + tig*2;
            #pragma unroll
            for (int half = 0; half < 2; half++) {
                int mm = m0 + m_base + mt*16 + gid + half*8;
                float v0 = acc[mt][nt][half*2];
                float v1 = acc[mt][nt][half*2 + 1];
                if (T.Cn2 && n >= T.nsplit) {
                    int nn = n - T.nsplit;
                    *(float2*)(T.Cn2 + (long)mm*T.ldCn2 + nn) = make_float2(v0, v1);
                } else {
                    if (T.bias) { v0 += T.bias[n]; v1 += T.bias[n+1]; }
                    if (T.C)
                        *(float2*)(T.C + (long)mm*T.ldC + n) = make_float2(v0, v1);
                    if (T.Chi) {
                        bf16 h0 = __float2bfloat16_rn(v0);
                        bf16 h1 = __float2bfloat16_rn(v1);
                        bf16 l0 = __float2bfloat16_rn(v0 - __bfloat162float(h0));
                        bf16 l1 = __float2bfloat16_rn(v1 - __bfloat162float(h1));
                        *(uint32_t*)(T.Chi + (long)mm*T.ldC + n) = pk2(h0, h1);
                        *(uint32_t*)(T.Clo + (long)mm*T.ldC + n) = pk2(l0, l1);
                        if (T.Cthi) {
                            T.Cthi[(long)n*T.ldCt + mm]       = h0;
                            T.Ctlo[(long)n*T.ldCt + mm]       = l0;
                            T.Cthi[(long)(n+1)*T.ldCt + mm]   = h1;
                            T.Ctlo[(long)(n+1)*T.ldCt + mm]   = l1;
                        }
                    }
                }
            }
        }
    }
}

// ========================= split / transpose kernels ========================
__global__ void split_kernel(STaskSet ts)
{
    int b = blockIdx.x, ti = 0;
    while (b >= ts.t[ti].blocks) { b -= ts.t[ti].blocks; ti++; }
    const STask S = ts.t[ti];
    long idx = ((long)b * 256 + threadIdx.x) * 8;
    float4 u = *(const float4*)(S.src + idx);
    float4 v = *(const float4*)(S.src + idx + 4);
    uint4 hi, lo;
    split8(u, v, hi, lo);
    *(uint4*)(S.hi + idx) = hi;
    *(uint4*)(S.lo + idx) = lo;
}

// z=0: A -> AThi/lo ; z=1: attn_out_w -> AoThi/lo
__global__ void transpose_split_kernel(const float* __restrict__ A,
                                       bf16* __restrict__ athi, bf16* __restrict__ atlo,
                                       const float* __restrict__ B,
                                       bf16* __restrict__ bthi, bf16* __restrict__ btlo)
{
    __shared__ float t[32][33];
    const float* src = blockIdx.z ? B : A;
    bf16* dh = blockIdx.z ? bthi : athi;
    bf16* dl = blockIdx.z ? btlo : atlo;
    int bx = blockIdx.x*32, by = blockIdx.y*32;
    int x = bx + threadIdx.x;
    #pragma unroll
    for (int i = 0; i < 32; i += 8) {
        int y = by + threadIdx.y + i;
        t[threadIdx.y + i][threadIdx.x] = src[(long)y*DD + x];
    }
    __syncthreads();
    int xo = by + threadIdx.x;
    #pragma unroll
    for (int i = 0; i < 32; i += 8) {
        int yo = bx + threadIdx.y + i;
        float v = t[threadIdx.x][threadIdx.y + i];
        bf16 h = __float2bfloat16_rn(v);
        dh[(long)yo*DD + xo] = h;
        dl[(long)yo*DD + xo] = __float2bfloat16_rn(v - __bfloat162float(h));
    }
}

// ========================= small SIMT kernels ===============================
__device__ __forceinline__ float sigf(float x) { return 1.0f / (1.0f + expf(-x)); }

// fused S1: blocks [0,256) delta; [256,768) pvec; [768,2304) lstm pointwise
__global__ void s1_kernel(const float* __restrict__ h1,
                          const float* __restrict__ dn_g,
                          const float* __restrict__ dn_beta,
                          const float* __restrict__ w2,
                          const float* __restrict__ b2,
                          float* __restrict__ delta,
                          const float* __restrict__ proj_w,
                          const float* __restrict__ aob,
                          const float* __restrict__ proj_b,
                          float* __restrict__ pvec,
                          const float* __restrict__ gA,
                          const float* __restrict__ gB,
                          const float* __restrict__ bih,
                          const float* __restrict__ bhh,
                          const float* __restrict__ lstm_c,
                          const float* __restrict__ decays,
                          float* __restrict__ h_new,
                          float* __restrict__ c_new,
                          bf16* __restrict__ hnh,
                          bf16* __restrict__ hnl)
{
    int blk = blockIdx.x, t = threadIdx.x;
    if (blk < 256) {
        __shared__ float red[256];
        int row = blk;
        const float* r = h1 + (long)row * DD;
        float x0 = r[t], x1 = r[t + 256];
        red[t] = x0 + x1; __syncthreads();
        for (int o = 128; o > 0; o >>= 1) { if (t < o) red[t] += red[t+o]; __syncthreads(); }
        float mean = red[0] * (1.0f/DD);
        __syncthreads();
        float d0 = x0 - mean, d1 = x1 - mean;
        red[t] = d0*d0 + d1*d1; __syncthreads();
        for (int o = 128; o > 0; o >>= 1) { if (t < o) red[t] += red[t+o]; __syncthreads(); }
        float inv = rsqrtf(red[0] * (1.0f/DD) + 1e-5f);
        __syncthreads();
        float y0 = d0 * inv * dn_g[t]     + dn_beta[t];
        float y1 = d1 * inv * dn_g[t+256] + dn_beta[t+256];
        y0 = 0.5f * y0 * (1.0f + erff(y0 * 0.70710678118654752f));
        y1 = 0.5f * y1 * (1.0f + erff(y1 * 0.70710678118654752f));
        red[t] = y0*w2[t] + y1*w2[t+256]; __syncthreads();
        for (int o = 128; o > 0; o >>= 1) { if (t < o) red[t] += red[t+o]; __syncthreads(); }
        if (t == 0) {
            float z = red[0] + b2[0];
            delta[row] = (z > 20.0f) ? z : log1pf(expf(z));
        }
    } else if (blk < 768) {
        __shared__ float red[256];
        int row = blk - 256;
        const float* r = proj_w + (long)row * 2560 + 512;
        red[t] = r[t]*aob[t] + r[t+256]*aob[t+256];
        __syncthreads();
        for (int o = 128; o > 0; o >>= 1) { if (t < o) red[t] += red[t+o]; __syncthreads(); }
        if (t == 0) pvec[row] = proj_b[row] + red[0];
    } else {
        int idx = (blk - 768) * 256 + t;
        int s = idx / (BB*DD);
        int r = idx - s * (BB*DD);
        int b = r >> 9;
        int d = r & 511;
        long gbase = ((long)s * BB + b) * 2048;
        const float* a = gA + gbase;
        const float* h = gB + gbase;
        const float* bi = bih + s*2048;
        const float* bh = bhh + s*2048;
        float ip = a[d]      + h[d]      + bi[d]      + bh[d];
        float fp = a[512+d]  + h[512+d]  + bi[512+d]  + bh[512+d];
        float gp = a[1024+d] + h[1024+d] + bi[1024+d] + bh[1024+d];
        float op = a[1536+d] + h[1536+d] + bi[1536+d] + bh[1536+d];
        float i_g = sigf(ip);
        float f_g = sigf(fp);
        float g_g = tanhf(gp);
        float o_g = sigf(op);
        float c   = lstm_c[idx];
        float craw = f_g * c + i_g * g_g;
        float hn   = o_g * tanhf(craw);
        float dec  = decays[s];
        h_new[idx] = hn;
        c_new[idx] = dec * c + (1.0f - dec) * craw;
        bf16 hh = __float2bfloat16_rn(hn);
        hnh[idx] = hh;
        hnl[idx] = __float2bfloat16_rn(hn - __bfloat162float(hh));
    }
}

// chain epilogue: U [256, nt*512]; emits T hi/lo; last emits y + hssm hi/lo
__global__ void chain_epilogue_kernel(const float* __restrict__ U,
                                      const float* __restrict__ delta,
                                      bf16* __restrict__ Th,
                                      bf16* __restrict__ Tl,
                                      float* __restrict__ y,
                                      const float* __restrict__ h_prev,
                                      int k0, int nt,
                                      const float* __restrict__ bx,
                                      bf16* __restrict__ yh,
                                      bf16* __restrict__ yl,
                                      int last)
{
    int idx = blockIdx.x * blockDim.x + threadIdx.x;
    if (idx >= BB*DD) return;
    int b = idx >> 9, n = idx & 511;
    const float* u0 = U + (long)b * (nt*512) + n;
    float d  = delta[b];
    float c  = 1.0f;
    float yy = (k0 == 0) ? h_prev[idx] : y[idx];
    float tl = 0.0f;
    for (int j = 0; j < nt; j++) {
        float u = u0[j*512];
        c *= d / (float)(k0 + j + 1);
        tl = c * u;
        yy += tl;
    }
    if (last) {
        yy += d * bx[idx];
        bf16 h = __float2bfloat16_rn(yy);
        yh[idx] = h;
        yl[idx] = __float2bfloat16_rn(yy - __bfloat162float(h));
    } else {
        bf16 h = __float2bfloat16_rn(tl);
        Th[idx] = h;
        Tl[idx] = __float2bfloat16_rn(tl - __bfloat162float(h));
    }
    y[idx] = yy;
}

// attention; consumes kv/q split-K partials + biases, emits ctx hi/lo
__global__ void attn_kernel(const float* __restrict__ qp,
                            const float* __restrict__ kvp,
                            const float* __restrict__ attn_in_b,
                            bf16* __restrict__ cxh,
                            bf16* __restrict__ cxl)
{
    int b    = blockIdx.x;
    int warp = threadIdx.x >> 5;
    int lane = threadIdx.x & 31;
    const long QP = (long)BB*DD;
    const long KP = (long)SS*BB*2*DD;

    long qo = (long)b * DD + warp * 64;
    float q0 = qp[qo + lane]      + qp[QP + qo + lane]      + attn_in_b[warp*64 + lane];
    float q1 = qp[qo + lane + 32] + qp[QP + qo + lane + 32] + attn_in_b[warp*64 + lane + 32];

    float sc[SS];
    #pragma unroll
    for (int s = 0; s < SS; s++) {
        long ko = (long)(s*BB + b) * 1024 + warp * 64;
        float k0 = kvp[ko + lane]      + kvp[KP + ko + lane]
                 + attn_in_b[512 + warp*64 + lane];
        float k1 = kvp[ko + lane + 32] + kvp[KP + ko + lane + 32]
                 + attn_in_b[512 + warp*64 + lane + 32];
        float d = q0 * k0 + q1 * k1;
        #pragma unroll
        for (int o = 16; o > 0; o >>= 1) d += __shfl_xor_sync(0xffffffff, d, o);
        sc[s] = d * 0.125f;
    }
    float m = fmaxf(sc[0], fmaxf(sc[1], sc[2]));
    float e[SS], sum = 0.0f;
    #pragma unroll
    for (int s = 0; s < SS; s++) { e[s] = expf(sc[s] - m); sum += e[s]; }
    float inv = 1.0f / sum;

    float c0 = 0.0f, c1 = 0.0f;
    #pragma unroll
    for (int s = 0; s < SS; s++) {
        long vo = (long)(s*BB + b) * 1024 + 512 + warp * 64;
        float v0 = kvp[vo + lane]      + kvp[KP + vo + lane]
                 + attn_in_b[1024 + warp*64 + lane];
        float v1 = kvp[vo + lane + 32] + kvp[KP + vo + lane + 32]
                 + attn_in_b[1024 + warp*64 + lane + 32];
        float w = e[s] * inv;
        c0 += w * v0;
        c1 += w * v1;
    }
    long o0 = (long)b * DD + warp*64 + lane;
    bf16 h0 = __float2bfloat16_rn(c0);
    bf16 h1 = __float2bfloat16_rn(c1);
    cxh[o0]      = h0;
    cxl[o0]      = __float2bfloat16_rn(c0 - __bfloat162float(h0));
    cxh[o0 + 32] = h1;
    cxl[o0 + 32] = __float2bfloat16_rn(c1 - __bfloat162float(h1));
}

// sum 10 proj partial planes + pvec -> layernorm -> out
__global__ void proj_ln_kernel(const float* __restrict__ part,
                               const float* __restrict__ pvec,
                               const float* __restrict__ g,
                               const float* __restrict__ be,
                               float* __restrict__ out)
{
    __shared__ float red[256];
    int row = blockIdx.x, t = threadIdx.x;
    long o0 = (long)row*DD + t, o1 = o0 + 256;
    const long PL = (long)BB*DD;
    float x0 = pvec[t], x1 = pvec[t+256];
    #pragma unroll
    for (int p = 0; p < 10; p++) { x0 += part[p*PL + o0]; x1 += part[p*PL + o1]; }

    red[t] = x0 + x1; __syncthreads();
    for (int o = 128; o > 0; o >>= 1) { if (t < o) red[t] += red[t+o]; __syncthreads(); }
    float mean = red[0] * (1.0f/DD);
    __syncthreads();

    float d0 = x0 - mean, d1 = x1 - mean;
    red[t] = d0*d0 + d1*d1; __syncthreads();
    for (int o = 128; o > 0; o >>= 1) { if (t < o) red[t] += red[t+o]; __syncthreads(); }
    float inv = rsqrtf(red[0] * (1.0f/DD) + 1e-5f);

    out[o0] = d0 * inv * g[t]     + be[t];
    out[o1] = d1 * inv * g[t+256] + be[t+256];
}

// ---------------------------------------------------------------------------
static inline GTask mk_task(const bf16* Xhi, const bf16* Xlo, int ldX,
                            const bf16* Whi, const bf16* Wlo, int ldW,
                            float* C, int ldC, int K, int kofs,
                            int mtiles, int ntiles)
{
    GTask t = {};
    t.Xhi = Xhi; t.Xlo = Xlo; t.ldX = ldX;
    t.Whi = Whi; t.Wlo = Wlo; t.ldW = ldW;
    t.C = C; t.ldC = ldC;
    t.K = K; t.kofs = kofs; t.nsplit = NOSPLIT;
    t.mtiles = mtiles; t.blocks = mtiles*ntiles;
    return t;
}

extern "C" void kernel_launch(void* const* d_in, const int* in_sizes, int n_in,
                              void* d_out, int out_size)
{
    (void)in_sizes; (void)n_in; (void)out_size;

    const float* x        = (const float*)d_in[0];
    const float* h_prev   = (const float*)d_in[1];
    const float* lstm_h   = (const float*)d_in[2];
    const float* lstm_c   = (const float*)d_in[3];
    const float* A        = (const float*)d_in[4];
    const float* Bm       = (const float*)d_in[5];
    const float* dn_w1    = (const float*)d_in[6];
    const float* dn_b1    = (const float*)d_in[7];
    const float* dn_g     = (const float*)d_in[8];
    const float* dn_beta  = (const float*)d_in[9];
    const float* dn_w2    = (const float*)d_in[10];
    const float* dn_b2    = (const float*)d_in[11];
    const float* lstm_wih = (const float*)d_in[12];
    const float* lstm_whh = (const float*)d_in[13];
    const float* lstm_bih = (const float*)d_in[14];
    const float* lstm_bhh = (const float*)d_in[15];
    const float* decays   = (const float*)d_in[16];
    const float* attn_in_w  = (const float*)d_in[17];
    const float* attn_in_b  = (const float*)d_in[18];
    const float* attn_out_w = (const float*)d_in[19];
    const float* attn_out_b = (const float*)d_in[20];
    const float* proj_w   = (const float*)d_in[21];
    const float* proj_b   = (const float*)d_in[22];
    const float* proj_g   = (const float*)d_in[23];
    const float* proj_beta= (const float*)d_in[24];

    float* out = (float*)d_out;
    float* out_y    = out;
    float* out_hssm = out + BB*DD;
    float* out_hnew = out + 2*BB*DD;
    float* out_cnew = out + 2*BB*DD + SS*BB*DD;

    // fp32 scratch
    float *p_h1, *p_delta, *p_bx, *p_U, *p_gA, *p_gB, *p_kvp, *p_qp, *p_part, *p_pvec;
    cudaGetSymbolAddress((void**)&p_h1,    g_h1);
    cudaGetSymbolAddress((void**)&p_delta, g_delta);
    cudaGetSymbolAddress((void**)&p_bx,    g_bx);
    cudaGetSymbolAddress((void**)&p_U,     g_U);
    cudaGetSymbolAddress((void**)&p_gA,    g_gA);
    cudaGetSymbolAddress((void**)&p_gB,    g_gB);
    cudaGetSymbolAddress((void**)&p_kvp,   g_kvp);
    cudaGetSymbolAddress((void**)&p_qp,    g_qp);
    cudaGetSymbolAddress((void**)&p_part,  g_part);
    cudaGetSymbolAddress((void**)&p_pvec,  g_pvec);

    // bf16 planes
    bf16 *xh,*xl,*hph,*hpl,*lhh,*lhl,*w1h,*w1l,*bmh,*bml,*wihh,*wihl,*whhh,*whhl,
         *aiwh,*aiwl,*pwh,*pwl,*wpowh,*wpowl,*ath,*atl,*a2th,*a2tl,*a4th,*a4tl,
         *aoth,*aotl,*mh,*ml,*th,*tl,*hsh,*hsl,*hnh,*hnl,*cxh,*cxl;
    cudaGetSymbolAddress((void**)&xh, g_xh);     cudaGetSymbolAddress((void**)&xl, g_xl);
    cudaGetSymbolAddress((void**)&hph, g_hph);   cudaGetSymbolAddress((void**)&hpl, g_hpl);
    cudaGetSymbolAddress((void**)&lhh, g_lhh);   cudaGetSymbolAddress((void**)&lhl, g_lhl);
    cudaGetSymbolAddress((void**)&w1h, g_w1h);   cudaGetSymbolAddress((void**)&w1l, g_w1l);
    cudaGetSymbolAddress((void**)&bmh, g_bmh);   cudaGetSymbolAddress((void**)&bml, g_bml);
    cudaGetSymbolAddress((void**)&wihh, g_wihh); cudaGetSymbolAddress((void**)&wihl, g_wihl);
    cudaGetSymbolAddress((void**)&whhh, g_whhh); cudaGetSymbolAddress((void**)&whhl, g_whhl);
    cudaGetSymbolAddress((void**)&aiwh, g_aiwh); cudaGetSymbolAddress((void**)&aiwl, g_aiwl);
    cudaGetSymbolAddress((void**)&pwh, g_pwh);   cudaGetSymbolAddress((void**)&pwl, g_pwl);
    cudaGetSymbolAddress((void**)&wpowh, g_wpowh); cudaGetSymbolAddress((void**)&wpowl, g_wpowl);
    cudaGetSymbolAddress((void**)&ath, g_ath);   cudaGetSymbolAddress((void**)&atl, g_atl);
    cudaGetSymbolAddress((void**)&a2th, g_a2th); cudaGetSymbolAddress((void**)&a2tl, g_a2tl);
    cudaGetSymbolAddress((void**)&a4th, g_a4th); cudaGetSymbolAddress((void**)&a4tl, g_a4tl);
    cudaGetSymbolAddress((void**)&aoth, g_aoth); cudaGetSymbolAddress((void**)&aotl, g_aotl);
    cudaGetSymbolAddress((void**)&mh, g_mh);     cudaGetSymbolAddress((void**)&ml, g_ml);
    cudaGetSymbolAddress((void**)&th, g_th);     cudaGetSymbolAddress((void**)&tl, g_tl);
    cudaGetSymbolAddress((void**)&hsh, g_hsh);   cudaGetSymbolAddress((void**)&hsl, g_hsl);
    cudaGetSymbolAddress((void**)&hnh, g_hnh);   cudaGetSymbolAddress((void**)&hnl, g_hnl);
    cudaGetSymbolAddress((void**)&cxh, g_cxh);   cudaGetSymbolAddress((void**)&cxl, g_cxl);

    cudaFuncSetAttribute(gemm_mma,
        cudaFuncAttributeMaxDynamicSharedMemorySize, SMEM_SZ);

    const long W2 = (long)DD*DD;
    const long KP = (long)SS*BB*2*DD;

    // ---- T0: transposes (A^T, attn_out_w^T) ----
    transpose_split_kernel<<<dim3(16,16,2), dim3(32,8)>>>(
        A, ath, atl, attn_out_w, aoth, aotl);

    // ---- T1: split all static operands (once) ----
    {
        STaskSet st = {};
        auto add = [&](int i, const float* s, bf16* h, bf16* l, long n) {
            st.t[i] = { s, h, l, (int)(n / 2048) };
        };
        add(0, x,        xh,   xl,   (long)BB*DD);
        add(1, h_prev,   hph,  hpl,  (long)BB*DD);
        add(2, lstm_h,   lhh,  lhl,  (long)SS*BB*DD);
        add(3, dn_w1,    w1h,  w1l,  W2);
        add(4, Bm,       bmh,  bml,  W2);
        add(5, lstm_wih, wihh, wihl, (long)SS*4*W2);
        add(6, lstm_whh, whhh, whhl, (long)SS*4*W2);
        add(7, attn_in_w, aiwh, aiwl, 3*W2);
        add(8, proj_w,   pwh,  pwl,  5*W2);
        add(9, A,        wpowh, wpowl, W2);
        st.ntasks = 10;
        int total = 0;
        for (int i = 0; i < 10; i++) total += st.t[i].blocks;
        split_kernel<<<total, 256>>>(st);
    }

    // ---- G1 (480 blocks): h1|bx, 6 lstm partials, A^2 (+A2T), M ----
    {
        GTaskSet ts = {};
        GTask t0 = mk_task(xh, xl, DD, w1h, w1l, DD, p_h1, DD, DD, 0, 2, 16);
        t0.bias = dn_b1; t0.Wn2hi = bmh; t0.Wn2lo = bml;
        t0.Cn2 = p_bx; t0.ldCn2 = DD; t0.nsplit = DD;
        ts.t[0] = t0;
        for (int s = 0; s < SS; s++) {
            ts.t[1+s] = mk_task(xh, xl, DD, wihh + (long)s*4*W2, wihl + (long)s*4*W2, DD,
                                p_gA + (long)s*BB*4*DD, 4*DD, DD, 0, 2, 32);
            ts.t[4+s] = mk_task(lhh + (long)s*BB*DD, lhl + (long)s*BB*DD, DD,
                                whhh + (long)s*4*W2, whhl + (long)s*4*W2, DD,
                                p_gB + (long)s*BB*4*DD, 4*DD, DD, 0, 2, 32);
        }
        GTask ta = mk_task(wpowh, wpowl, DD, ath, atl, DD, nullptr, DD, DD, 0, 4, 8);
        ta.Chi = wpowh + W2; ta.Clo = wpowl + W2;
        ta.Cthi = a2th; ta.Ctlo = a2tl; ta.ldCt = DD;
        ts.t[7] = ta;
        GTask tm = mk_task(pwh + 512, pwl + 512, 5*DD, aoth, aotl, DD,
                           nullptr, DD, DD, 0, 4, 8);
        tm.Chi = mh; tm.Clo = ml;
        ts.t[8] = tm;
        ts.ntasks = 9;
        gemm_mma<<<480, 256, SMEM_SZ>>>(ts);
    }

    // ---- S1 fused: delta, pvec, lstm pointwise (+h_new hi/lo) ----
    s1_kernel<<<2304, 256>>>(p_h1, dn_g, dn_beta, dn_w2, dn_b2, p_delta,
                             proj_w, attn_out_b, proj_b, p_pvec,
                             p_gA, p_gB, lstm_bih, lstm_bhh, lstm_c, decays,
                             out_hnew, out_cnew, hnh, hnl);

    // ---- G2 (256 blocks): A^3, A^4 (+A4T), kv split-K-2 ----
    {
        GTaskSet ts = {};
        GTask t3 = mk_task(wpowh + W2, wpowl + W2, DD, ath, atl, DD,
                           nullptr, DD, DD, 0, 4, 8);
        t3.Chi = wpowh + 2*W2; t3.Clo = wpowl + 2*W2;
        ts.t[0] = t3;
        GTask t4 = mk_task(wpowh + W2, wpowl + W2, DD, a2th, a2tl, DD,
                           nullptr, DD, DD, 0, 4, 8);
        t4.Chi = wpowh + 3*W2; t4.Clo = wpowl + 3*W2;
        t4.Cthi = a4th; t4.Ctlo = a4tl; t4.ldCt = DD;
        ts.t[1] = t4;
        for (int kz = 0; kz < 2; kz++)
            ts.t[2+kz] = mk_task(hnh, hnl, DD, aiwh + W2, aiwl + W2, DD,
                                 p_kvp + (long)kz*KP, 2*DD, 256, kz*256, 6, 16);
        ts.ntasks = 4;
        gemm_mma<<<256, 256, SMEM_SZ>>>(ts);
    }

    // ---- G3 (224 blocks): A^5..A^8, h_new proj partials (planes 4..9) ----
    {
        GTaskSet ts = {};
        GTask t5 = mk_task(wpowh + 3*W2, wpowl + 3*W2, DD, ath, atl, DD,
                           nullptr, DD, DD, 0, 4, 8);
        t5.Chi = wpowh + 4*W2; t5.Clo = wpowl + 4*W2;
        ts.t[0] = t5;
        GTask t6 = mk_task(wpowh + 3*W2, wpowl + 3*W2, DD, a2th, a2tl, DD,
                           nullptr, DD, DD, 0, 4, 8);
        t6.Chi = wpowh + 5*W2; t6.Clo = wpowl + 5*W2;
        ts.t[1] = t6;
        GTask t7 = mk_task(wpowh + 2*W2, wpowl + 2*W2, DD, a4th, a4tl, DD,
                           nullptr, DD, DD, 0, 4, 8);
        t7.Chi = wpowh + 6*W2; t7.Clo = wpowl + 6*W2;
        ts.t[2] = t7;
        GTask t8 = mk_task(wpowh + 3*W2, wpowl + 3*W2, DD, a4th, a4tl, DD,
                           nullptr, DD, DD, 0, 4, 8);
        t8.Chi = wpowh + 7*W2; t8.Clo = wpowl + 7*W2;
        ts.t[3] = t8;
        int p = 0;
        for (int i = 0; i < SS; i++)
            for (int kz = 0; kz < 2; kz++, p++)
                ts.t[4+p] = mk_task(hnh + (long)i*BB*DD, hnl + (long)i*BB*DD, DD,
                                    pwh + 1024 + i*512, pwl + 1024 + i*512, 5*DD,
                                    p_part + (long)(4 + p)*BB*DD, DD,
                                    256, kz*256, 2, 8);
        ts.ntasks = 10;
        gemm_mma<<<224, 256, SMEM_SZ>>>(ts);
    }

    // ---- chain: 2 iters x 8 terms (KT=16) ----
    {
        GTaskSet ts = {};
        ts.t[0] = mk_task(hph, hpl, DD, wpowh, wpowl, DD, p_U, 8*DD, DD, 0, 2, 64);
        ts.ntasks = 1;
        gemm_mma<<<128, 256, SMEM_SZ>>>(ts);
    }
    chain_epilogue_kernel<<<(BB*DD)/256, 256>>>(
        p_U, p_delta, th, tl, out_hssm, h_prev, 0, 8, p_bx, hsh, hsl, 0);
    {
        GTaskSet ts = {};
        ts.t[0] = mk_task(th, tl, DD, wpowh, wpowl, DD, p_U, 8*DD, DD, 0, 2, 64);
        ts.ntasks = 1;
        gemm_mma<<<128, 256, SMEM_SZ>>>(ts);
    }
    chain_epilogue_kernel<<<(BB*DD)/256, 256>>>(
        p_U, p_delta, th, tl, out_hssm, h_prev, 8, 8, p_bx, hsh, hsl, 1);

    // ---- G4 (64 blocks): q split-K-2 + hssm proj (planes 0,1) ----
    {
        GTaskSet ts = {};
        for (int kz = 0; kz < 2; kz++) {
            ts.t[kz] = mk_task(hsh, hsl, DD, aiwh, aiwl, DD,
                               p_qp + (long)kz*BB*DD, DD, 256, kz*256, 2, 8);
            ts.t[2+kz] = mk_task(hsh, hsl, DD, pwh, pwl, 5*DD,
                                 p_part + (long)kz*BB*DD, DD, 256, kz*256, 2, 8);
        }
        ts.ntasks = 4;
        gemm_mma<<<64, 256, SMEM_SZ>>>(ts);
    }

    // ---- attention (emits ctx hi/lo) ----
    attn_kernel<<<BB, 256>>>(p_qp, p_kvp, attn_in_b, cxh, cxl);

    // ---- G5 (32 blocks): ctx @ M^T -> planes 2,3 ----
    {
        GTaskSet ts = {};
        for (int kz = 0; kz < 2; kz++)
            ts.t[kz] = mk_task(cxh, cxl, DD, mh, ml, DD,
                               p_part + (long)(2+kz)*BB*DD, DD, 256, kz*256, 2, 8);
        ts.ntasks = 2;
        gemm_mma<<<32, 256, SMEM_SZ>>>(ts);
    }

    // ---- reduce + LN -> out_y ----
    proj_ln_kernel<<<BB, 256>>>(p_part, p_pvec, proj_g, proj_beta, out_y);
}

// round 11
// speedup vs baseline: 1.0183x; 1.0183x over previous
#include <cuda_runtime.h>
#include <cuda_bf16.h>
#include <math.h>
#include <cstdint>

// ---------------------------------------------------------------------------
// SSMXLSTMFusion: D=512, S=3, BATCH=256, H=8, HD=64
// Round 11: persistent grid-barrier phases. Chain (2 GEMM iters + epilogues)
// in ONE launch with register-resident y; tail (q/hssm-proj GEMM -> attn ->
// ctx GEMM -> proj+LN) in ONE launch. 7 launches total. Pre-split bf16 hi/lo
// operands, cp.async GEMM, KT=16 Taylor (A^1..A^8).
// ---------------------------------------------------------------------------

#define DD    512
#define BB    256
#define SS    3
typedef __nv_bfloat16 bf16;

// ------------------------- fp32 scratch ------------------------------------
__device__ float g_h1   [BB*DD];
__device__ float g_delta[BB];
__device__ float g_bx   [BB*DD];
__device__ float g_U    [BB*8*DD];
__device__ float g_gA   [SS*BB*4*DD];
__device__ float g_gB   [SS*BB*4*DD];
__device__ float g_kvp  [2*SS*BB*2*DD];
__device__ float g_qp   [2*BB*DD];
__device__ float g_part [10*BB*DD];
__device__ float g_pvec [DD];

// ------------------------- bf16 hi/lo planes --------------------------------
__device__ bf16 g_xh[BB*DD],          g_xl[BB*DD];
__device__ bf16 g_hph[BB*DD],         g_hpl[BB*DD];
__device__ bf16 g_lhh[SS*BB*DD],      g_lhl[SS*BB*DD];
__device__ bf16 g_w1h[DD*DD],         g_w1l[DD*DD];
__device__ bf16 g_bmh[DD*DD],         g_bml[DD*DD];
__device__ bf16 g_wihh[SS*4*DD*DD],   g_wihl[SS*4*DD*DD];
__device__ bf16 g_whhh[SS*4*DD*DD],   g_whhl[SS*4*DD*DD];
__device__ bf16 g_aiwh[3*DD*DD],      g_aiwl[3*DD*DD];
__device__ bf16 g_pwh[DD*5*DD],       g_pwl[DD*5*DD];
__device__ bf16 g_wpowh[8*DD*DD],     g_wpowl[8*DD*DD];
__device__ bf16 g_ath[DD*DD],         g_atl[DD*DD];
__device__ bf16 g_a2th[DD*DD],        g_a2tl[DD*DD];
__device__ bf16 g_a4th[DD*DD],        g_a4tl[DD*DD];
__device__ bf16 g_aoth[DD*DD],        g_aotl[DD*DD];
__device__ bf16 g_mh[DD*DD],          g_ml[DD*DD];
__device__ bf16 g_th[BB*DD],          g_tl[BB*DD];
__device__ bf16 g_hsh[BB*DD],         g_hsl[BB*DD];
__device__ bf16 g_hnh[SS*BB*DD],      g_hnl[SS*BB*DD];
__device__ bf16 g_cxh[BB*DD],         g_cxl[BB*DD];

// grid barriers (separate per persistent kernel)
__device__ volatile unsigned g_gen1; __device__ unsigned g_cnt1;
__device__ volatile unsigned g_gen2; __device__ unsigned g_cnt2;

// ========================= descriptors ======================================
struct GTask {
    const bf16 *Xhi, *Xlo, *Whi, *Wlo, *Wn2hi, *Wn2lo;
    const float* bias;
    float *C, *Cn2;
    bf16 *Chi, *Clo, *Cthi, *Ctlo;
    int ldX, ldW, ldC, ldCn2, ldCt;
    int K, kofs, nsplit, mtiles, blocks;
};
struct GTaskSet { GTask t[12]; int ntasks; };

struct STask { const float* src; bf16 *hi, *lo; int blocks; };
struct STaskSet { STask t[12]; int ntasks; };

#define NOSPLIT (1<<30)

// ========================= smem layout ======================================
#define RSB     80
#define OFF_AHI 0
#define OFF_ALO 10240
#define OFF_BHI 20480
#define OFF_BLO 25600
#define STAGE   30720
#define SMEM_SZ (3*STAGE)      // 92160 bytes

__device__ __forceinline__ uint32_t smem_to_u32(const void* p) {
    uint32_t a;
    asm("{ .reg .u64 t; cvta.to.shared.u64 t, %1; cvt.u32.u64 %0, t; }"
        : "=r"(a) : "l"(p));
    return a;
}

__device__ __forceinline__ uint32_t pk2(bf16 a, bf16 b) {
    uint16_t ua = *(uint16_t*)&a, ub = *(uint16_t*)&b;
    return (uint32_t)ua | ((uint32_t)ub << 16);
}

__device__ __forceinline__ void split8(float4 u, float4 v, uint4& hi, uint4& lo)
{
    float f[8] = {u.x,u.y,u.z,u.w,v.x,v.y,v.z,v.w};
    uint32_t h[4], l[4];
    #pragma unroll
    for (int i = 0; i < 4; i++) {
        bf16 b0 = __float2bfloat16_rn(f[2*i]);
        bf16 b1 = __float2bfloat16_rn(f[2*i+1]);
        bf16 r0 = __float2bfloat16_rn(f[2*i]   - __bfloat162float(b0));
        bf16 r1 = __float2bfloat16_rn(f[2*i+1] - __bfloat162float(b1));
        h[i] = pk2(b0, b1);
        l[i] = pk2(r0, r1);
    }
    hi = make_uint4(h[0], h[1], h[2], h[3]);
    lo = make_uint4(l[0], l[1], l[2], l[3]);
}

__device__ __forceinline__ void ldm_x4(uint32_t* r, uint32_t addr) {
    asm volatile("ldmatrix.sync.aligned.m8n8.x4.shared.b16 {%0,%1,%2,%3}, [%4];"
        : "=r"(r[0]), "=r"(r[1]), "=r"(r[2]), "=r"(r[3]) : "r"(addr));
}

__device__ __forceinline__ void mma_bf16(float* c, const uint32_t* a, const uint32_t* b)
{
    asm volatile(
        "mma.sync.aligned.m16n8k16.row.col.f32.bf16.bf16.f32 "
        "{%0,%1,%2,%3}, {%4,%5,%6,%7}, {%8,%9}, {%0,%1,%2,%3};"
        : "+f"(c[0]), "+f"(c[1]), "+f"(c[2]), "+f"(c[3])
        : "r"(a[0]), "r"(a[1]), "r"(a[2]), "r"(a[3]), "r"(b[0]), "r"(b[1]));
}

#define CP16(saddr, gaddr) \
    asm volatile("cp.async.cg.shared.global [%0], [%1], 16;" \
        :: "r"(saddr), "l"(gaddr) : "memory")

// ------------------------- grid barriers ------------------------------------
__device__ __forceinline__ void grid_barrier(volatile unsigned* gen,
                                             unsigned* cnt, unsigned total)
{
    __syncthreads();
    if (threadIdx.x == 0) {
        unsigned mygen = *gen;
        __threadfence();
        unsigned t = atomicAdd(cnt, 1u);
        if (t == total - 1) {
            *cnt = 0;
            __threadfence();
            *gen = mygen + 1;
        } else {
            while (*gen == mygen) { __nanosleep(32); }
            __threadfence();
        }
    }
    __syncthreads();
}

// ------------------------- GEMM tile (device) --------------------------------
__device__ __forceinline__ void issue_chunk(const GTask& T, uint32_t smb,
    int m0, int n0, int tid, int k0, int stage)
{
    const uint32_t sb = smb + (uint32_t)(stage * STAGE);
    #pragma unroll
    for (int j = 0; j < 4; j++) {
        int o  = tid + j*256;
        int pl = o >> 9;
        int r  = (o >> 2) & 127;
        int s  = o & 3;
        const bf16* g = (pl ? T.Xlo : T.Xhi) + (long)(m0 + r) * T.ldX + k0 + s*8;
        uint32_t sa = sb + (uint32_t)(pl*10240 + r*80 + s*16);
        CP16(sa, g);
    }
    #pragma unroll
    for (int j = 0; j < 2; j++) {
        int o  = tid + j*256;
        int pl = o >> 8;
        int r  = (o >> 2) & 63;
        int s  = o & 3;
        int ng = n0 + r;
        const bf16* w;
        if (ng >= T.nsplit)
            w = (pl ? T.Wn2lo : T.Wn2hi) + (long)(ng - T.nsplit) * T.ldW;
        else
            w = (pl ? T.Wlo : T.Whi) + (long)ng * T.ldW;
        uint32_t sa = sb + (uint32_t)(20480 + pl*5120 + r*80 + s*16);
        CP16(sa, w + k0 + s*8);
    }
    asm volatile("cp.async.commit_group;" ::: "memory");
}

// full 128x64 tile: mainloop + epilogue. All 256 threads participate.
__device__ void gemm_tile(const GTask& T, int b, char* smem)
{
    const int m0 = (b % T.mtiles) * 128;
    const int n0 = (b / T.mtiles) * 64;

    const int tid = threadIdx.x;
    const int lid = tid & 31;
    const int wid = tid >> 5;
    const int m_base = (wid & 3) * 32;
    const int n_base = (wid >> 2) * 32;
    const int gid = lid >> 2;
    const int tig = lid & 3;
    const int g  = lid >> 3;
    const int ig = lid & 7;

    const uint32_t smb = smem_to_u32(smem);
    const uint32_t a_ad = smb + (uint32_t)((m_base + (g&1)*8 + ig) * RSB + (g>>1)*16);
    const uint32_t b_ad = smb + (uint32_t)((n_base + (g>>1)*8 + ig) * RSB + (g&1)*16);

    float acc[2][4][4];
    #pragma unroll
    for (int i = 0; i < 2; i++)
        #pragma unroll
        for (int j = 0; j < 4; j++)
            #pragma unroll
            for (int k = 0; k < 4; k++) acc[i][j][k] = 0.0f;

    const int nc = T.K >> 5;

    issue_chunk(T, smb, m0, n0, tid, T.kofs, 0);
    if (nc > 1) issue_chunk(T, smb, m0, n0, tid, T.kofs + 32, 1);

    for (int c = 0; c < nc; c++) {
        if (c + 1 < nc)
            asm volatile("cp.async.wait_group 1;" ::: "memory");
        else
            asm volatile("cp.async.wait_group 0;" ::: "memory");
        __syncthreads();

        if (c + 2 < nc)
            issue_chunk(T, smb, m0, n0, tid, T.kofs + (c+2)*32, (c+2)%3);

        const uint32_t sb = (uint32_t)((c % 3) * STAGE);
        #pragma unroll
        for (int ks = 0; ks < 2; ks++) {
            const uint32_t kb = sb + ks * 32;
            uint32_t ahi[2][4], alo[2][4], bhi[4][2], blo[4][2];
            #pragma unroll
            for (int mt = 0; mt < 2; mt++) {
                ldm_x4(ahi[mt], a_ad + OFF_AHI + mt*16*RSB + kb);
                ldm_x4(alo[mt], a_ad + OFF_ALO + mt*16*RSB + kb);
            }
            #pragma unroll
            for (int np = 0; np < 2; np++) {
                uint32_t r[4];
                ldm_x4(r, b_ad + OFF_BHI + np*16*RSB + kb);
                bhi[2*np][0] = r[0]; bhi[2*np][1] = r[1];
                bhi[2*np+1][0] = r[2]; bhi[2*np+1][1] = r[3];
                ldm_x4(r, b_ad + OFF_BLO + np*16*RSB + kb);
                blo[2*np][0] = r[0]; blo[2*np][1] = r[1];
                blo[2*np+1][0] = r[2]; blo[2*np+1][1] = r[3];
            }
            #pragma unroll
            for (int mt = 0; mt < 2; mt++)
                #pragma unroll
                for (int nt = 0; nt < 4; nt++) {
                    mma_bf16(acc[mt][nt], ahi[mt], bhi[nt]);
                    mma_bf16(acc[mt][nt], ahi[mt], blo[nt]);
                    mma_bf16(acc[mt][nt], alo[mt], bhi[nt]);
                }
        }
        __syncthreads();
    }

    #pragma unroll
    for (int mt = 0; mt < 2; mt++) {
        #pragma unroll
        for (int nt = 0; nt < 4; nt++) {
            int n = n0 + n_base + nt*8 + tig*2;
            #pragma unroll
            for (int half = 0; half < 2; half++) {
                int mm = m0 + m_base + mt*16 + gid + half*8;
                float v0 = acc[mt][nt][half*2];
                float v1 = acc[mt][nt][half*2 + 1];
                if (T.Cn2 && n >= T.nsplit) {
                    int nn = n - T.nsplit;
                    *(float2*)(T.Cn2 + (long)mm*T.ldCn2 + nn) = make_float2(v0, v1);
                } else {
                    if (T.bias) { v0 += T.bias[n]; v1 += T.bias[n+1]; }
                    if (T.C)
                        *(float2*)(T.C + (long)mm*T.ldC + n) = make_float2(v0, v1);
                    if (T.Chi) {
                        bf16 h0 = __float2bfloat16_rn(v0);
                        bf16 h1 = __float2bfloat16_rn(v1);
                        bf16 l0 = __float2bfloat16_rn(v0 - __bfloat162float(h0));
                        bf16 l1 = __float2bfloat16_rn(v1 - __bfloat162float(h1));
                        *(uint32_t*)(T.Chi + (long)mm*T.ldC + n) = pk2(h0, h1);
                        *(uint32_t*)(T.Clo + (long)mm*T.ldC + n) = pk2(l0, l1);
                        if (T.Cthi) {
                            T.Cthi[(long)n*T.ldCt + mm]       = h0;
                            T.Ctlo[(long)n*T.ldCt + mm]       = l0;
                            T.Cthi[(long)(n+1)*T.ldCt + mm]   = h1;
                            T.Ctlo[(long)(n+1)*T.ldCt + mm]   = l1;
                        }
                    }
                }
            }
        }
    }
}

// ========================= batched GEMM launch ==============================
__global__ void __launch_bounds__(256, 2)
gemm_mma(GTaskSet ts)
{
    extern __shared__ char smem[];
    int b = blockIdx.x, ti = 0;
    while (b >= ts.t[ti].blocks) { b -= ts.t[ti].blocks; ti++; }
    gemm_tile(ts.t[ti], b, smem);
}

// ========================= prep: split + transposes =========================
__global__ void prep_kernel(STaskSet ts, int split_blocks,
                            const float* __restrict__ A,
                            bf16* __restrict__ athi, bf16* __restrict__ atlo,
                            const float* __restrict__ B,
                            bf16* __restrict__ bthi, bf16* __restrict__ btlo)
{
    int b = blockIdx.x;
    if (b < split_blocks) {
        int ti = 0;
        while (b >= ts.t[ti].blocks) { b -= ts.t[ti].blocks; ti++; }
        const STask S = ts.t[ti];
        long idx = ((long)b * 256 + threadIdx.x) * 8;
        float4 u = *(const float4*)(S.src + idx);
        float4 v = *(const float4*)(S.src + idx + 4);
        uint4 hi, lo;
        split8(u, v, hi, lo);
        *(uint4*)(S.hi + idx) = hi;
        *(uint4*)(S.lo + idx) = lo;
        return;
    }
    // transpose blocks: 512 of them (2 x 16 x 16), 256 threads = 32x8
    int tb = b - split_blocks;
    int z  = tb >> 8;
    int rem = tb & 255;
    int bx = (rem & 15) * 32, by = (rem >> 4) * 32;
    int tx = threadIdx.x & 31, ty = threadIdx.x >> 5;
    __shared__ float t[32][33];
    const float* src = z ? B : A;
    bf16* dh = z ? bthi : athi;
    bf16* dl = z ? btlo : atlo;
    int x = bx + tx;
    #pragma unroll
    for (int i = 0; i < 32; i += 8) {
        int y = by + ty + i;
        t[ty + i][tx] = src[(long)y*DD + x];
    }
    __syncthreads();
    int xo = by + tx;
    #pragma unroll
    for (int i = 0; i < 32; i += 8) {
        int yo = bx + ty + i;
        float v = t[tx][ty + i];
        bf16 h = __float2bfloat16_rn(v);
        dh[(long)yo*DD + xo] = h;
        dl[(long)yo*DD + xo] = __float2bfloat16_rn(v - __bfloat162float(h));
    }
}

// ========================= S1 fused ==========================================
__device__ __forceinline__ float sigf(float x) { return 1.0f / (1.0f + expf(-x)); }

__global__ void s1_kernel(const float* __restrict__ h1,
                          const float* __restrict__ dn_g,
                          const float* __restrict__ dn_beta,
                          const float* __restrict__ w2,
                          const float* __restrict__ b2,
                          float* __restrict__ delta,
                          const float* __restrict__ proj_w,
                          const float* __restrict__ aob,
                          const float* __restrict__ proj_b,
                          float* __restrict__ pvec,
                          const float* __restrict__ gA,
                          const float* __restrict__ gB,
                          const float* __restrict__ bih,
                          const float* __restrict__ bhh,
                          const float* __restrict__ lstm_c,
                          const float* __restrict__ decays,
                          float* __restrict__ h_new,
                          float* __restrict__ c_new,
                          bf16* __restrict__ hnh,
                          bf16* __restrict__ hnl)
{
    int blk = blockIdx.x, t = threadIdx.x;
    if (blk < 256) {
        __shared__ float red[256];
        int row = blk;
        const float* r = h1 + (long)row * DD;
        float x0 = r[t], x1 = r[t + 256];
        red[t] = x0 + x1; __syncthreads();
        for (int o = 128; o > 0; o >>= 1) { if (t < o) red[t] += red[t+o]; __syncthreads(); }
        float mean = red[0] * (1.0f/DD);
        __syncthreads();
        float d0 = x0 - mean, d1 = x1 - mean;
        red[t] = d0*d0 + d1*d1; __syncthreads();
        for (int o = 128; o > 0; o >>= 1) { if (t < o) red[t] += red[t+o]; __syncthreads(); }
        float inv = rsqrtf(red[0] * (1.0f/DD) + 1e-5f);
        __syncthreads();
        float y0 = d0 * inv * dn_g[t]     + dn_beta[t];
        float y1 = d1 * inv * dn_g[t+256] + dn_beta[t+256];
        y0 = 0.5f * y0 * (1.0f + erff(y0 * 0.70710678118654752f));
        y1 = 0.5f * y1 * (1.0f + erff(y1 * 0.70710678118654752f));
        red[t] = y0*w2[t] + y1*w2[t+256]; __syncthreads();
        for (int o = 128; o > 0; o >>= 1) { if (t < o) red[t] += red[t+o]; __syncthreads(); }
        if (t == 0) {
            float z = red[0] + b2[0];
            delta[row] = (z > 20.0f) ? z : log1pf(expf(z));
        }
    } else if (blk < 768) {
        __shared__ float red[256];
        int row = blk - 256;
        const float* r = proj_w + (long)row * 2560 + 512;
        red[t] = r[t]*aob[t] + r[t+256]*aob[t+256];
        __syncthreads();
        for (int o = 128; o > 0; o >>= 1) { if (t < o) red[t] += red[t+o]; __syncthreads(); }
        if (t == 0) pvec[row] = proj_b[row] + red[0];
    } else {
        int idx = (blk - 768) * 256 + t;
        int s = idx / (BB*DD);
        int r = idx - s * (BB*DD);
        int b = r >> 9;
        int d = r & 511;
        long gbase = ((long)s * BB + b) * 2048;
        const float* a = gA + gbase;
        const float* h = gB + gbase;
        const float* bi = bih + s*2048;
        const float* bh = bhh + s*2048;
        float ip = a[d]      + h[d]      + bi[d]      + bh[d];
        float fp = a[512+d]  + h[512+d]  + bi[512+d]  + bh[512+d];
        float gp = a[1024+d] + h[1024+d] + bi[1024+d] + bh[1024+d];
        float op = a[1536+d] + h[1536+d] + bi[1536+d] + bh[1536+d];
        float i_g = sigf(ip);
        float f_g = sigf(fp);
        float g_g = tanhf(gp);
        float o_g = sigf(op);
        float c   = lstm_c[idx];
        float craw = f_g * c + i_g * g_g;
        float hn   = o_g * tanhf(craw);
        float dec  = decays[s];
        h_new[idx] = hn;
        c_new[idx] = dec * c + (1.0f - dec) * craw;
        bf16 hh = __float2bfloat16_rn(hn);
        hnh[idx] = hh;
        hnl[idx] = __float2bfloat16_rn(hn - __bfloat162float(hh));
    }
}

// ========================= persistent chain kernel ===========================
// 128 blocks: iter1 GEMM(h_prev @ Wpow, N=4096) -> barrier -> epilogue ->
// barrier -> iter2 GEMM(T @ Wpow) -> barrier -> final epilogue.
// y accumulator lives in registers (fixed element ownership).
__global__ void __launch_bounds__(256, 2)
chain_kernel(const bf16* __restrict__ hph, const bf16* __restrict__ hpl,
             const bf16* __restrict__ wpowh, const bf16* __restrict__ wpowl,
             float* __restrict__ U,
             bf16* __restrict__ th, bf16* __restrict__ tl,
             const float* __restrict__ delta,
             const float* __restrict__ h_prev,
             const float* __restrict__ bx,
             float* __restrict__ out_hssm,
             bf16* __restrict__ hsh, bf16* __restrict__ hsl)
{
    extern __shared__ char smem[];
    const int tid = threadIdx.x;
    const long idx0 = ((long)blockIdx.x * 256 + tid) * 4;
    const int row = (int)(idx0 >> 9);
    const int col = (int)(idx0 & 511);
    const float dval = delta[row];

    float y[4];
    *(float4*)y = *(const float4*)(h_prev + idx0);

    for (int iter = 0; iter < 2; iter++) {
        GTask T = {};
        T.Xhi = iter ? th : hph;  T.Xlo = iter ? tl : hpl;  T.ldX = DD;
        T.Whi = wpowh;            T.Wlo = wpowl;            T.ldW = DD;
        T.C = U; T.ldC = 8*DD;
        T.K = DD; T.kofs = 0; T.nsplit = NOSPLIT; T.mtiles = 2;
        gemm_tile(T, blockIdx.x, smem);

        grid_barrier(&g_gen1, &g_cnt1, 128);

        // epilogue: 4 owned elements, 8 terms each
        const int k0 = iter * 8;
        const float* u0 = U + (long)row * 4096 + col;
        float c = 1.0f, tlast[4];
        #pragma unroll
        for (int e = 0; e < 4; e++) tlast[e] = 0.0f;
        for (int j = 0; j < 8; j++) {
            c *= dval / (float)(k0 + j + 1);
            #pragma unroll
            for (int e = 0; e < 4; e++) {
                float term = c * u0[j*512 + e];
                tlast[e] = term;
                y[e] += term;
            }
        }
        if (iter == 0) {
            #pragma unroll
            for (int e = 0; e < 4; e++) {
                bf16 h = __float2bfloat16_rn(tlast[e]);
                th[idx0 + e] = h;
                tl[idx0 + e] = __float2bfloat16_rn(tlast[e] - __bfloat162float(h));
            }
            grid_barrier(&g_gen1, &g_cnt1, 128);
        } else {
            #pragma unroll
            for (int e = 0; e < 4; e++) {
                float yy = y[e] + dval * bx[idx0 + e];
                out_hssm[idx0 + e] = yy;
                bf16 h = __float2bfloat16_rn(yy);
                hsh[idx0 + e] = h;
                hsl[idx0 + e] = __float2bfloat16_rn(yy - __bfloat162float(h));
            }
        }
    }
}

// ========================= persistent tail kernel ============================
// 256 blocks: [G4: q splitK2 + hssm-proj] -> barrier -> attn -> barrier ->
// [G5: ctx @ M splitK2] -> barrier -> proj reduce + LN.
__global__ void __launch_bounds__(256, 2)
tail_kernel(const bf16* __restrict__ hsh, const bf16* __restrict__ hsl,
            const bf16* __restrict__ aiwh, const bf16* __restrict__ aiwl,
            const bf16* __restrict__ pwh, const bf16* __restrict__ pwl,
            const bf16* __restrict__ mh, const bf16* __restrict__ ml,
            float* __restrict__ qp, float* __restrict__ kvp,
            float* __restrict__ part,
            const float* __restrict__ attn_in_b,
            bf16* __restrict__ cxh, bf16* __restrict__ cxl,
            const float* __restrict__ pvec,
            const float* __restrict__ pg, const float* __restrict__ pbe,
            float* __restrict__ out_y)
{
    extern __shared__ char smem[];
    const int tid = threadIdx.x;
    const int blk = blockIdx.x;

    // ---- phase A: G4 (64 blocks busy) ----
    if (blk < 64) {
        int b = blk;
        GTask T = {};
        T.ldX = DD; T.nsplit = NOSPLIT; T.mtiles = 2; T.K = 256;
        T.Xhi = hsh; T.Xlo = hsl;
        if (b < 32) {           // q split-K2: kz = b/16
            int kz = b >> 4;
            T.Whi = aiwh; T.Wlo = aiwl; T.ldW = DD;
            T.C = qp + (long)kz*BB*DD; T.ldC = DD; T.kofs = kz*256;
            gemm_tile(T, b & 15, smem);
        } else {                // hssm proj split-K2
            int b2 = b - 32;
            int kz = b2 >> 4;
            T.Whi = pwh; T.Wlo = pwl; T.ldW = 5*DD;
            T.C = part + (long)kz*BB*DD; T.ldC = DD; T.kofs = kz*256;
            gemm_tile(T, b2 & 15, smem);
        }
    }
    grid_barrier(&g_gen2, &g_cnt2, 256);

    // ---- phase B: attention (all 256 blocks; block = batch b) ----
    {
        int b    = blk;
        int warp = tid >> 5;
        int lane = tid & 31;
        const long QP = (long)BB*DD;
        const long KP = (long)SS*BB*2*DD;

        long qo = (long)b * DD + warp * 64;
        float q0 = qp[qo + lane]      + qp[QP + qo + lane]      + attn_in_b[warp*64 + lane];
        float q1 = qp[qo + lane + 32] + qp[QP + qo + lane + 32] + attn_in_b[warp*64 + lane + 32];

        float sc[SS];
        #pragma unroll
        for (int s = 0; s < SS; s++) {
            long ko = (long)(s*BB + b) * 1024 + warp * 64;
            float k0 = kvp[ko + lane]      + kvp[KP + ko + lane]
                     + attn_in_b[512 + warp*64 + lane];
            float k1 = kvp[ko + lane + 32] + kvp[KP + ko + lane + 32]
                     + attn_in_b[512 + warp*64 + lane + 32];
            float d = q0 * k0 + q1 * k1;
            #pragma unroll
            for (int o = 16; o > 0; o >>= 1) d += __shfl_xor_sync(0xffffffff, d, o);
            sc[s] = d * 0.125f;
        }
        float m = fmaxf(sc[0], fmaxf(sc[1], sc[2]));
        float e[SS], sum = 0.0f;
        #pragma unroll
        for (int s = 0; s < SS; s++) { e[s] = expf(sc[s] - m); sum += e[s]; }
        float inv = 1.0f / sum;

        float c0 = 0.0f, c1 = 0.0f;
        #pragma unroll
        for (int s = 0; s < SS; s++) {
            long vo = (long)(s*BB + b) * 1024 + 512 + warp * 64;
            float v0 = kvp[vo + lane]      + kvp[KP + vo + lane]
                     + attn_in_b[1024 + warp*64 + lane];
            float v1 = kvp[vo + lane + 32] + kvp[KP + vo + lane + 32]
                     + attn_in_b[1024 + warp*64 + lane + 32];
            float w = e[s] * inv;
            c0 += w * v0;
            c1 += w * v1;
        }
        long o0 = (long)b * DD + warp*64 + lane;
        bf16 h0 = __float2bfloat16_rn(c0);
        bf16 h1 = __float2bfloat16_rn(c1);
        cxh[o0]      = h0;
        cxl[o0]      = __float2bfloat16_rn(c0 - __bfloat162float(h0));
        cxh[o0 + 32] = h1;
        cxl[o0 + 32] = __float2bfloat16_rn(c1 - __bfloat162float(h1));
    }
    grid_barrier(&g_gen2, &g_cnt2, 256);

    // ---- phase C: G5 ctx @ M (32 blocks busy) ----
    if (blk < 32) {
        int kz = blk >> 4;
        GTask T = {};
        T.Xhi = cxh; T.Xlo = cxl; T.ldX = DD;
        T.Whi = mh; T.Wlo = ml; T.ldW = DD;
        T.C = part + (long)(2+kz)*BB*DD; T.ldC = DD;
        T.K = 256; T.kofs = kz*256; T.nsplit = NOSPLIT; T.mtiles = 2;
        gemm_tile(T, blk & 15, smem);
    }
    grid_barrier(&g_gen2, &g_cnt2, 256);

    // ---- phase D: proj reduce + LN (256 blocks; block = row) ----
    {
        float* red = (float*)smem;
        int row = blk, t = tid;
        long o0 = (long)row*DD + t, o1 = o0 + 256;
        const long PL = (long)BB*DD;
        float x0 = pvec[t], x1 = pvec[t+256];
        #pragma unroll
        for (int p = 0; p < 10; p++) { x0 += part[p*PL + o0]; x1 += part[p*PL + o1]; }

        red[t] = x0 + x1; __syncthreads();
        for (int o = 128; o > 0; o >>= 1) { if (t < o) red[t] += red[t+o]; __syncthreads(); }
        float mean = red[0] * (1.0f/DD);
        __syncthreads();

        float d0 = x0 - mean, d1 = x1 - mean;
        red[t] = d0*d0 + d1*d1; __syncthreads();
        for (int o = 128; o > 0; o >>= 1) { if (t < o) red[t] += red[t+o]; __syncthreads(); }
        float inv = rsqrtf(red[0] * (1.0f/DD) + 1e-5f);

        out_y[o0] = d0 * inv * pg[t]     + pbe[t];
        out_y[o1] = d1 * inv * pg[t+256] + pbe[t+256];
    }
}

// ---------------------------------------------------------------------------
static inline GTask mk_task(const bf16* Xhi, const bf16* Xlo, int ldX,
                            const bf16* Whi, const bf16* Wlo, int ldW,
                            float* C, int ldC, int K, int kofs,
                            int mtiles, int ntiles)
{
    GTask t = {};
    t.Xhi = Xhi; t.Xlo = Xlo; t.ldX = ldX;
    t.Whi = Whi; t.Wlo = Wlo; t.ldW = ldW;
    t.C = C; t.ldC = ldC;
    t.K = K; t.kofs = kofs; t.nsplit = NOSPLIT;
    t.mtiles = mtiles; t.blocks = mtiles*ntiles;
    return t;
}

extern "C" void kernel_launch(void* const* d_in, const int* in_sizes, int n_in,
                              void* d_out, int out_size)
{
    (void)in_sizes; (void)n_in; (void)out_size;

    const float* x        = (const float*)d_in[0];
    const float* h_prev   = (const float*)d_in[1];
    const float* lstm_h   = (const float*)d_in[2];
    const float* lstm_c   = (const float*)d_in[3];
    const float* A        = (const float*)d_in[4];
    const float* Bm       = (const float*)d_in[5];
    const float* dn_w1    = (const float*)d_in[6];
    const float* dn_b1    = (const float*)d_in[7];
    const float* dn_g     = (const float*)d_in[8];
    const float* dn_beta  = (const float*)d_in[9];
    const float* dn_w2    = (const float*)d_in[10];
    const float* dn_b2    = (const float*)d_in[11];
    const float* lstm_wih = (const float*)d_in[12];
    const float* lstm_whh = (const float*)d_in[13];
    const float* lstm_bih = (const float*)d_in[14];
    const float* lstm_bhh = (const float*)d_in[15];
    const float* decays   = (const float*)d_in[16];
    const float* attn_in_w  = (const float*)d_in[17];
    const float* attn_in_b  = (const float*)d_in[18];
    const float* attn_out_w = (const float*)d_in[19];
    const float* attn_out_b = (const float*)d_in[20];
    const float* proj_w   = (const float*)d_in[21];
    const float* proj_b   = (const float*)d_in[22];
    const float* proj_g   = (const float*)d_in[23];
    const float* proj_beta= (const float*)d_in[24];

    float* out = (float*)d_out;
    float* out_y    = out;
    float* out_hssm = out + BB*DD;
    float* out_hnew = out + 2*BB*DD;
    float* out_cnew = out + 2*BB*DD + SS*BB*DD;

    float *p_h1, *p_delta, *p_bx, *p_U, *p_gA, *p_gB, *p_kvp, *p_qp, *p_part, *p_pvec;
    cudaGetSymbolAddress((void**)&p_h1,    g_h1);
    cudaGetSymbolAddress((void**)&p_delta, g_delta);
    cudaGetSymbolAddress((void**)&p_bx,    g_bx);
    cudaGetSymbolAddress((void**)&p_U,     g_U);
    cudaGetSymbolAddress((void**)&p_gA,    g_gA);
    cudaGetSymbolAddress((void**)&p_gB,    g_gB);
    cudaGetSymbolAddress((void**)&p_kvp,   g_kvp);
    cudaGetSymbolAddress((void**)&p_qp,    g_qp);
    cudaGetSymbolAddress((void**)&p_part,  g_part);
    cudaGetSymbolAddress((void**)&p_pvec,  g_pvec);

    bf16 *xh,*xl,*hph,*hpl,*lhh,*lhl,*w1h,*w1l,*bmh,*bml,*wihh,*wihl,*whhh,*whhl,
         *aiwh,*aiwl,*pwh,*pwl,*wpowh,*wpowl,*ath,*atl,*a2th,*a2tl,*a4th,*a4tl,
         *aoth,*aotl,*mh,*ml,*th,*tl,*hsh,*hsl,*hnh,*hnl,*cxh,*cxl;
    cudaGetSymbolAddress((void**)&xh, g_xh);     cudaGetSymbolAddress((void**)&xl, g_xl);
    cudaGetSymbolAddress((void**)&hph, g_hph);   cudaGetSymbolAddress((void**)&hpl, g_hpl);
    cudaGetSymbolAddress((void**)&lhh, g_lhh);   cudaGetSymbolAddress((void**)&lhl, g_lhl);
    cudaGetSymbolAddress((void**)&w1h, g_w1h);   cudaGetSymbolAddress((void**)&w1l, g_w1l);
    cudaGetSymbolAddress((void**)&bmh, g_bmh);   cudaGetSymbolAddress((void**)&bml, g_bml);
    cudaGetSymbolAddress((void**)&wihh, g_wihh); cudaGetSymbolAddress((void**)&wihl, g_wihl);
    cudaGetSymbolAddress((void**)&whhh, g_whhh); cudaGetSymbolAddress((void**)&whhl, g_whhl);
    cudaGetSymbolAddress((void**)&aiwh, g_aiwh); cudaGetSymbolAddress((void**)&aiwl, g_aiwl);
    cudaGetSymbolAddress((void**)&pwh, g_pwh);   cudaGetSymbolAddress((void**)&pwl, g_pwl);
    cudaGetSymbolAddress((void**)&wpowh, g_wpowh); cudaGetSymbolAddress((void**)&wpowl, g_wpowl);
    cudaGetSymbolAddress((void**)&ath, g_ath);   cudaGetSymbolAddress((void**)&atl, g_atl);
    cudaGetSymbolAddress((void**)&a2th, g_a2th); cudaGetSymbolAddress((void**)&a2tl, g_a2tl);
    cudaGetSymbolAddress((void**)&a4th, g_a4th); cudaGetSymbolAddress((void**)&a4tl, g_a4tl);
    cudaGetSymbolAddress((void**)&aoth, g_aoth); cudaGetSymbolAddress((void**)&aotl, g_aotl);
    cudaGetSymbolAddress((void**)&mh, g_mh);     cudaGetSymbolAddress((void**)&ml, g_ml);
    cudaGetSymbolAddress((void**)&th, g_th);     cudaGetSymbolAddress((void**)&tl, g_tl);
    cudaGetSymbolAddress((void**)&hsh, g_hsh);   cudaGetSymbolAddress((void**)&hsl, g_hsl);
    cudaGetSymbolAddress((void**)&hnh, g_hnh);   cudaGetSymbolAddress((void**)&hnl, g_hnl);
    cudaGetSymbolAddress((void**)&cxh, g_cxh);   cudaGetSymbolAddress((void**)&cxl, g_cxl);

    cudaFuncSetAttribute(gemm_mma,
        cudaFuncAttributeMaxDynamicSharedMemorySize, SMEM_SZ);
    cudaFuncSetAttribute(chain_kernel,
        cudaFuncAttributeMaxDynamicSharedMemorySize, SMEM_SZ);
    cudaFuncSetAttribute(tail_kernel,
        cudaFuncAttributeMaxDynamicSharedMemorySize, SMEM_SZ);

    const long W2 = (long)DD*DD;
    const long KP = (long)SS*BB*2*DD;

    // ---- K1: split all operands + transposes (one launch) ----
    {
        STaskSet st = {};
        auto add = [&](int i, const float* s, bf16* h, bf16* l, long n) {
            st.t[i] = { s, h, l, (int)(n / 2048) };
        };
        add(0, x,        xh,   xl,   (long)BB*DD);
        add(1, h_prev,   hph,  hpl,  (long)BB*DD);
        add(2, lstm_h,   lhh,  lhl,  (long)SS*BB*DD);
        add(3, dn_w1,    w1h,  w1l,  W2);
        add(4, Bm,       bmh,  bml,  W2);
        add(5, lstm_wih, wihh, wihl, (long)SS*4*W2);
        add(6, lstm_whh, whhh, whhl, (long)SS*4*W2);
        add(7, attn_in_w, aiwh, aiwl, 3*W2);
        add(8, proj_w,   pwh,  pwl,  5*W2);
        add(9, A,        wpowh, wpowl, W2);
        st.ntasks = 10;
        int total = 0;
        for (int i = 0; i < 10; i++) total += st.t[i].blocks;
        prep_kernel<<<total + 512, 256>>>(st, total,
            A, ath, atl, attn_out_w, aoth, aotl);
    }

    // ---- K2 (G1, 480 blocks): h1|bx, 6 lstm partials, A^2 (+A2T), M ----
    {
        GTaskSet ts = {};
        GTask t0 = mk_task(xh, xl, DD, w1h, w1l, DD, p_h1, DD, DD, 0, 2, 16);
        t0.bias = dn_b1; t0.Wn2hi = bmh; t0.Wn2lo = bml;
        t0.Cn2 = p_bx; t0.ldCn2 = DD; t0.nsplit = DD;
        ts.t[0] = t0;
        for (int s = 0; s < SS; s++) {
            ts.t[1+s] = mk_task(xh, xl, DD, wihh + (long)s*4*W2, wihl + (long)s*4*W2, DD,
                                p_gA + (long)s*BB*4*DD, 4*DD, DD, 0, 2, 32);
            ts.t[4+s] = mk_task(lhh + (long)s*BB*DD, lhl + (long)s*BB*DD, DD,
                                whhh + (long)s*4*W2, whhl + (long)s*4*W2, DD,
                                p_gB + (long)s*BB*4*DD, 4*DD, DD, 0, 2, 32);
        }
        GTask ta = mk_task(wpowh, wpowl, DD, ath, atl, DD, nullptr, DD, DD, 0, 4, 8);
        ta.Chi = wpowh + W2; ta.Clo = wpowl + W2;
        ta.Cthi = a2th; ta.Ctlo = a2tl; ta.ldCt = DD;
        ts.t[7] = ta;
        GTask tm = mk_task(pwh + 512, pwl + 512, 5*DD, aoth, aotl, DD,
                           nullptr, DD, DD, 0, 4, 8);
        tm.Chi = mh; tm.Clo = ml;
        ts.t[8] = tm;
        ts.ntasks = 9;
        gemm_mma<<<480, 256, SMEM_SZ>>>(ts);
    }

    // ---- K3: S1 fused (delta, pvec, lstm pointwise) ----
    s1_kernel<<<2304, 256>>>(p_h1, dn_g, dn_beta, dn_w2, dn_b2, p_delta,
                             proj_w, attn_out_b, proj_b, p_pvec,
                             p_gA, p_gB, lstm_bih, lstm_bhh, lstm_c, decays,
                             out_hnew, out_cnew, hnh, hnl);

    // ---- K4 (G2, 256 blocks): A^3, A^4 (+A4T), kv split-K-2 ----
    {
        GTaskSet ts = {};
        GTask t3 = mk_task(wpowh + W2, wpowl + W2, DD, ath, atl, DD,
                           nullptr, DD, DD, 0, 4, 8);
        t3.Chi = wpowh + 2*W2; t3.Clo = wpowl + 2*W2;
        ts.t[0] = t3;
        GTask t4 = mk_task(wpowh + W2, wpowl + W2, DD, a2th, a2tl, DD,
                           nullptr, DD, DD, 0, 4, 8);
        t4.Chi = wpowh + 3*W2; t4.Clo = wpowl + 3*W2;
        t4.Cthi = a4th; t4.Ctlo = a4tl; t4.ldCt = DD;
        ts.t[1] = t4;
        for (int kz = 0; kz < 2; kz++)
            ts.t[2+kz] = mk_task(hnh, hnl, DD, aiwh + W2, aiwl + W2, DD,
                                 p_kvp + (long)kz*KP, 2*DD, 256, kz*256, 6, 16);
        ts.ntasks = 4;
        gemm_mma<<<256, 256, SMEM_SZ>>>(ts);
    }

    // ---- K5 (G3, 224 blocks): A^5..A^8, h_new proj partials (planes 4..9) ----
    {
        GTaskSet ts = {};
        GTask t5 = mk_task(wpowh + 3*W2, wpowl + 3*W2, DD, ath, atl, DD,
                           nullptr, DD, DD, 0, 4, 8);
        t5.Chi = wpowh + 4*W2; t5.Clo = wpowl + 4*W2;
        ts.t[0] = t5;
        GTask t6 = mk_task(wpowh + 3*W2, wpowl + 3*W2, DD, a2th, a2tl, DD,
                           nullptr, DD, DD, 0, 4, 8);
        t6.Chi = wpowh + 5*W2; t6.Clo = wpowl + 5*W2;
        ts.t[1] = t6;
        GTask t7 = mk_task(wpowh + 2*W2, wpowl + 2*W2, DD, a4th, a4tl, DD,
                           nullptr, DD, DD, 0, 4, 8);
        t7.Chi = wpowh + 6*W2; t7.Clo = wpowl + 6*W2;
        ts.t[2] = t7;
        GTask t8 = mk_task(wpowh + 3*W2, wpowl + 3*W2, DD, a4th, a4tl, DD,
                           nullptr, DD, DD, 0, 4, 8);
        t8.Chi = wpowh + 7*W2; t8.Clo = wpowl + 7*W2;
        ts.t[3] = t8;
        int p = 0;
        for (int i = 0; i < SS; i++)
            for (int kz = 0; kz < 2; kz++, p++)
                ts.t[4+p] = mk_task(hnh + (long)i*BB*DD, hnl + (long)i*BB*DD, DD,
                                    pwh + 1024 + i*512, pwl + 1024 + i*512, 5*DD,
                                    p_part + (long)(4 + p)*BB*DD, DD,
                                    256, kz*256, 2, 8);
        ts.ntasks = 10;
        gemm_mma<<<224, 256, SMEM_SZ>>>(ts);
    }

    // ---- K6: persistent chain (both iterations + epilogues) ----
    chain_kernel<<<128, 256, SMEM_SZ>>>(hph, hpl, wpowh, wpowl, p_U, th, tl,
                                        p_delta, h_prev, p_bx,
                                        out_hssm, hsh, hsl);

    // ---- K7: persistent tail (G4 -> attn -> G5 -> proj+LN) ----
    tail_kernel<<<256, 256, SMEM_SZ>>>(hsh, hsl, aiwh, aiwl, pwh, pwl, mh, ml,
                                       p_qp, p_kvp, p_part, attn_in_b,
                                       cxh, cxl, p_pvec, proj_g, proj_beta,
                                       out_y);
}

// round 12
// speedup vs baseline: 1.0668x; 1.0476x over previous
#include <cuda_runtime.h>
#include <cuda_bf16.h>
#include <math.h>
#include <cstdint>

// ---------------------------------------------------------------------------
// SSMXLSTMFusion: D=512, S=3, BATCH=256, H=8, HD=64
// Round 12: split-K everywhere inside the persistent phases so every GEMM
// wave fills >=256 blocks (2 CTAs/SM). Chain: 2 iters, split-K-2 (256 blk).
// Tail: q/hssm-proj split-K-4 (128 blk), ctx@M split-K-4 (64 blk).
// Pre-split bf16 hi/lo operands, cp.async GEMM, KT=16 Taylor (A^1..A^8).
// ---------------------------------------------------------------------------

#define DD    512
#define BB    256
#define SS    3
typedef __nv_bfloat16 bf16;

// ------------------------- fp32 scratch ------------------------------------
__device__ float g_h1   [BB*DD];
__device__ float g_delta[BB];
__device__ float g_bx   [BB*DD];
__device__ float g_U    [2*BB*8*DD];          // 2 split-K planes
__device__ float g_gA   [SS*BB*4*DD];
__device__ float g_gB   [SS*BB*4*DD];
__device__ float g_kvp  [2*SS*BB*2*DD];
__device__ float g_qp   [4*BB*DD];            // 4 split-K planes
__device__ float g_part [14*BB*DD];           // hssm 0-3, ctx 4-7, hnew 8-13
__device__ float g_pvec [DD];

// ------------------------- bf16 hi/lo planes --------------------------------
__device__ bf16 g_xh[BB*DD],          g_xl[BB*DD];
__device__ bf16 g_hph[BB*DD],         g_hpl[BB*DD];
__device__ bf16 g_lhh[SS*BB*DD],      g_lhl[SS*BB*DD];
__device__ bf16 g_w1h[DD*DD],         g_w1l[DD*DD];
__device__ bf16 g_bmh[DD*DD],         g_bml[DD*DD];
__device__ bf16 g_wihh[SS*4*DD*DD],   g_wihl[SS*4*DD*DD];
__device__ bf16 g_whhh[SS*4*DD*DD],   g_whhl[SS*4*DD*DD];
__device__ bf16 g_aiwh[3*DD*DD],      g_aiwl[3*DD*DD];
__device__ bf16 g_pwh[DD*5*DD],       g_pwl[DD*5*DD];
__device__ bf16 g_wpowh[8*DD*DD],     g_wpowl[8*DD*DD];
__device__ bf16 g_ath[DD*DD],         g_atl[DD*DD];
__device__ bf16 g_a2th[DD*DD],        g_a2tl[DD*DD];
__device__ bf16 g_a4th[DD*DD],        g_a4tl[DD*DD];
__device__ bf16 g_aoth[DD*DD],        g_aotl[DD*DD];
__device__ bf16 g_mh[DD*DD],          g_ml[DD*DD];
__device__ bf16 g_th[BB*DD],          g_tl[BB*DD];
__device__ bf16 g_hsh[BB*DD],         g_hsl[BB*DD];
__device__ bf16 g_hnh[SS*BB*DD],      g_hnl[SS*BB*DD];
__device__ bf16 g_cxh[BB*DD],         g_cxl[BB*DD];

__device__ volatile unsigned g_gen1; __device__ unsigned g_cnt1;
__device__ volatile unsigned g_gen2; __device__ unsigned g_cnt2;

// ========================= descriptors ======================================
struct GTask {
    const bf16 *Xhi, *Xlo, *Whi, *Wlo, *Wn2hi, *Wn2lo;
    const float* bias;
    float *C, *Cn2;
    bf16 *Chi, *Clo, *Cthi, *Ctlo;
    int ldX, ldW, ldC, ldCn2, ldCt;
    int K, kofs, nsplit, mtiles, blocks;
};
struct GTaskSet { GTask t[12]; int ntasks; };

struct STask { const float* src; bf16 *hi, *lo; int blocks; };
struct STaskSet { STask t[12]; int ntasks; };

#define NOSPLIT (1<<30)

// ========================= smem layout ======================================
#define RSB     80
#define OFF_AHI 0
#define OFF_ALO 10240
#define OFF_BHI 20480
#define OFF_BLO 25600
#define STAGE   30720
#define SMEM_SZ (3*STAGE)      // 92160 bytes

__device__ __forceinline__ uint32_t smem_to_u32(const void* p) {
    uint32_t a;
    asm("{ .reg .u64 t; cvta.to.shared.u64 t, %1; cvt.u32.u64 %0, t; }"
        : "=r"(a) : "l"(p));
    return a;
}

__device__ __forceinline__ uint32_t pk2(bf16 a, bf16 b) {
    uint16_t ua = *(uint16_t*)&a, ub = *(uint16_t*)&b;
    return (uint32_t)ua | ((uint32_t)ub << 16);
}

__device__ __forceinline__ void split8(float4 u, float4 v, uint4& hi, uint4& lo)
{
    float f[8] = {u.x,u.y,u.z,u.w,v.x,v.y,v.z,v.w};
    uint32_t h[4], l[4];
    #pragma unroll
    for (int i = 0; i < 4; i++) {
        bf16 b0 = __float2bfloat16_rn(f[2*i]);
        bf16 b1 = __float2bfloat16_rn(f[2*i+1]);
        bf16 r0 = __float2bfloat16_rn(f[2*i]   - __bfloat162float(b0));
        bf16 r1 = __float2bfloat16_rn(f[2*i+1] - __bfloat162float(b1));
        h[i] = pk2(b0, b1);
        l[i] = pk2(r0, r1);
    }
    hi = make_uint4(h[0], h[1], h[2], h[3]);
    lo = make_uint4(l[0], l[1], l[2], l[3]);
}

__device__ __forceinline__ void ldm_x4(uint32_t* r, uint32_t addr) {
    asm volatile("ldmatrix.sync.aligned.m8n8.x4.shared.b16 {%0,%1,%2,%3}, [%4];"
        : "=r"(r[0]), "=r"(r[1]), "=r"(r[2]), "=r"(r[3]) : "r"(addr));
}

__device__ __forceinline__ void mma_bf16(float* c, const uint32_t* a, const uint32_t* b)
{
    asm volatile(
        "mma.sync.aligned.m16n8k16.row.col.f32.bf16.bf16.f32 "
        "{%0,%1,%2,%3}, {%4,%5,%6,%7}, {%8,%9}, {%0,%1,%2,%3};"
        : "+f"(c[0]), "+f"(c[1]), "+f"(c[2]), "+f"(c[3])
        : "r"(a[0]), "r"(a[1]), "r"(a[2]), "r"(a[3]), "r"(b[0]), "r"(b[1]));
}

#define CP16(saddr, gaddr) \
    asm volatile("cp.async.cg.shared.global [%0], [%1], 16;" \
        :: "r"(saddr), "l"(gaddr) : "memory")

__device__ __forceinline__ void grid_barrier(volatile unsigned* gen,
                                             unsigned* cnt, unsigned total)
{
    __syncthreads();
    if (threadIdx.x == 0) {
        unsigned mygen = *gen;
        __threadfence();
        unsigned t = atomicAdd(cnt, 1u);
        if (t == total - 1) {
            *cnt = 0;
            __threadfence();
            *gen = mygen + 1;
        } else {
            while (*gen == mygen) { __nanosleep(32); }
            __threadfence();
        }
    }
    __syncthreads();
}

// ------------------------- GEMM tile (device) --------------------------------
__device__ __forceinline__ void issue_chunk(const GTask& T, uint32_t smb,
    int m0, int n0, int tid, int k0, int stage)
{
    const uint32_t sb = smb + (uint32_t)(stage * STAGE);
    #pragma unroll
    for (int j = 0; j < 4; j++) {
        int o  = tid + j*256;
        int pl = o >> 9;
        int r  = (o >> 2) & 127;
        int s  = o & 3;
        const bf16* g = (pl ? T.Xlo : T.Xhi) + (long)(m0 + r) * T.ldX + k0 + s*8;
        uint32_t sa = sb + (uint32_t)(pl*10240 + r*80 + s*16);
        CP16(sa, g);
    }
    #pragma unroll
    for (int j = 0; j < 2; j++) {
        int o  = tid + j*256;
        int pl = o >> 8;
        int r  = (o >> 2) & 63;
        int s  = o & 3;
        int ng = n0 + r;
        const bf16* w;
        if (ng >= T.nsplit)
            w = (pl ? T.Wn2lo : T.Wn2hi) + (long)(ng - T.nsplit) * T.ldW;
        else
            w = (pl ? T.Wlo : T.Whi) + (long)ng * T.ldW;
        uint32_t sa = sb + (uint32_t)(20480 + pl*5120 + r*80 + s*16);
        CP16(sa, w + k0 + s*8);
    }
    asm volatile("cp.async.commit_group;" ::: "memory");
}

__device__ void gemm_tile(const GTask& T, int b, char* smem)
{
    const int m0 = (b % T.mtiles) * 128;
    const int n0 = (b / T.mtiles) * 64;

    const int tid = threadIdx.x;
    const int lid = tid & 31;
    const int wid = tid >> 5;
    const int m_base = (wid & 3) * 32;
    const int n_base = (wid >> 2) * 32;
    const int gid = lid >> 2;
    const int tig = lid & 3;
    const int g  = lid >> 3;
    const int ig = lid & 7;

    const uint32_t smb = smem_to_u32(smem);
    const uint32_t a_ad = smb + (uint32_t)((m_base + (g&1)*8 + ig) * RSB + (g>>1)*16);
    const uint32_t b_ad = smb + (uint32_t)((n_base + (g>>1)*8 + ig) * RSB + (g&1)*16);

    float acc[2][4][4];
    #pragma unroll
    for (int i = 0; i < 2; i++)
        #pragma unroll
        for (int j = 0; j < 4; j++)
            #pragma unroll
            for (int k = 0; k < 4; k++) acc[i][j][k] = 0.0f;

    const int nc = T.K >> 5;

    issue_chunk(T, smb, m0, n0, tid, T.kofs, 0);
    if (nc > 1) issue_chunk(T, smb, m0, n0, tid, T.kofs + 32, 1);

    for (int c = 0; c < nc; c++) {
        if (c + 1 < nc)
            asm volatile("cp.async.wait_group 1;" ::: "memory");
        else
            asm volatile("cp.async.wait_group 0;" ::: "memory");
        __syncthreads();

        if (c + 2 < nc)
            issue_chunk(T, smb, m0, n0, tid, T.kofs + (c+2)*32, (c+2)%3);

        const uint32_t sb = (uint32_t)((c % 3) * STAGE);
        #pragma unroll
        for (int ks = 0; ks < 2; ks++) {
            const uint32_t kb = sb + ks * 32;
            uint32_t ahi[2][4], alo[2][4], bhi[4][2], blo[4][2];
            #pragma unroll
            for (int mt = 0; mt < 2; mt++) {
                ldm_x4(ahi[mt], a_ad + OFF_AHI + mt*16*RSB + kb);
                ldm_x4(alo[mt], a_ad + OFF_ALO + mt*16*RSB + kb);
            }
            #pragma unroll
            for (int np = 0; np < 2; np++) {
                uint32_t r[4];
                ldm_x4(r, b_ad + OFF_BHI + np*16*RSB + kb);
                bhi[2*np][0] = r[0]; bhi[2*np][1] = r[1];
                bhi[2*np+1][0] = r[2]; bhi[2*np+1][1] = r[3];
                ldm_x4(r, b_ad + OFF_BLO + np*16*RSB + kb);
                blo[2*np][0] = r[0]; blo[2*np][1] = r[1];
                blo[2*np+1][0] = r[2]; blo[2*np+1][1] = r[3];
            }
            #pragma unroll
            for (int mt = 0; mt < 2; mt++)
                #pragma unroll
                for (int nt = 0; nt < 4; nt++) {
                    mma_bf16(acc[mt][nt], ahi[mt], bhi[nt]);
                    mma_bf16(acc[mt][nt], ahi[mt], blo[nt]);
                    mma_bf16(acc[mt][nt], alo[mt], bhi[nt]);
                }
        }
        __syncthreads();
    }

    #pragma unroll
    for (int mt = 0; mt < 2; mt++) {
        #pragma unroll
        for (int nt = 0; nt < 4; nt++) {
            int n = n0 + n_base + nt*8 + tig*2;
            #pragma unroll
            for (int half = 0; half < 2; half++) {
                int mm = m0 + m_base + mt*16 + gid + half*8;
                float v0 = acc[mt][nt][half*2];
                float v1 = acc[mt][nt][half*2 + 1];
                if (T.Cn2 && n >= T.nsplit) {
                    int nn = n - T.nsplit;
                    *(float2*)(T.Cn2 + (long)mm*T.ldCn2 + nn) = make_float2(v0, v1);
                } else {
                    if (T.bias) { v0 += T.bias[n]; v1 += T.bias[n+1]; }
                    if (T.C)
                        *(float2*)(T.C + (long)mm*T.ldC + n) = make_float2(v0, v1);
                    if (T.Chi) {
                        bf16 h0 = __float2bfloat16_rn(v0);
                        bf16 h1 = __float2bfloat16_rn(v1);
                        bf16 l0 = __float2bfloat16_rn(v0 - __bfloat162float(h0));
                        bf16 l1 = __float2bfloat16_rn(v1 - __bfloat162float(h1));
                        *(uint32_t*)(T.Chi + (long)mm*T.ldC + n) = pk2(h0, h1);
                        *(uint32_t*)(T.Clo + (long)mm*T.ldC + n) = pk2(l0, l1);
                        if (T.Cthi) {
                            T.Cthi[(long)n*T.ldCt + mm]       = h0;
                            T.Ctlo[(long)n*T.ldCt + mm]       = l0;
                            T.Cthi[(long)(n+1)*T.ldCt + mm]   = h1;
                            T.Ctlo[(long)(n+1)*T.ldCt + mm]   = l1;
                        }
                    }
                }
            }
        }
    }
}

// ========================= batched GEMM launch ==============================
__global__ void __launch_bounds__(256, 2)
gemm_mma(GTaskSet ts)
{
    extern __shared__ char smem[];
    int b = blockIdx.x, ti = 0;
    while (b >= ts.t[ti].blocks) { b -= ts.t[ti].blocks; ti++; }
    gemm_tile(ts.t[ti], b, smem);
}

// ========================= prep: split + transposes =========================
__global__ void prep_kernel(STaskSet ts, int split_blocks,
                            const float* __restrict__ A,
                            bf16* __restrict__ athi, bf16* __restrict__ atlo,
                            const float* __restrict__ B,
                            bf16* __restrict__ bthi, bf16* __restrict__ btlo)
{
    int b = blockIdx.x;
    if (b < split_blocks) {
        int ti = 0;
        while (b >= ts.t[ti].blocks) { b -= ts.t[ti].blocks; ti++; }
        const STask S = ts.t[ti];
        long idx = ((long)b * 256 + threadIdx.x) * 8;
        float4 u = *(const float4*)(S.src + idx);
        float4 v = *(const float4*)(S.src + idx + 4);
        uint4 hi, lo;
        split8(u, v, hi, lo);
        *(uint4*)(S.hi + idx) = hi;
        *(uint4*)(S.lo + idx) = lo;
        return;
    }
    int tb = b - split_blocks;
    int z  = tb >> 8;
    int rem = tb & 255;
    int bx = (rem & 15) * 32, by = (rem >> 4) * 32;
    int tx = threadIdx.x & 31, ty = threadIdx.x >> 5;
    __shared__ float t[32][33];
    const float* src = z ? B : A;
    bf16* dh = z ? bthi : athi;
    bf16* dl = z ? btlo : atlo;
    int x = bx + tx;
    #pragma unroll
    for (int i = 0; i < 32; i += 8) {
        int y = by + ty + i;
        t[ty + i][tx] = src[(long)y*DD + x];
    }
    __syncthreads();
    int xo = by + tx;
    #pragma unroll
    for (int i = 0; i < 32; i += 8) {
        int yo = bx + ty + i;
        float v = t[tx][ty + i];
        bf16 h = __float2bfloat16_rn(v);
        dh[(long)yo*DD + xo] = h;
        dl[(long)yo*DD + xo] = __float2bfloat16_rn(v - __bfloat162float(h));
    }
}

// ========================= S1 fused ==========================================
__device__ __forceinline__ float sigf(float x) { return 1.0f / (1.0f + expf(-x)); }

__global__ void s1_kernel(const float* __restrict__ h1,
                          const float* __restrict__ dn_g,
                          const float* __restrict__ dn_beta,
                          const float* __restrict__ w2,
                          const float* __restrict__ b2,
                          float* __restrict__ delta,
                          const float* __restrict__ proj_w,
                          const float* __restrict__ aob,
                          const float* __restrict__ proj_b,
                          float* __restrict__ pvec,
                          const float* __restrict__ gA,
                          const float* __restrict__ gB,
                          const float* __restrict__ bih,
                          const float* __restrict__ bhh,
                          const float* __restrict__ lstm_c,
                          const float* __restrict__ decays,
                          float* __restrict__ h_new,
                          float* __restrict__ c_new,
                          bf16* __restrict__ hnh,
                          bf16* __restrict__ hnl)
{
    int blk = blockIdx.x, t = threadIdx.x;
    if (blk < 256) {
        __shared__ float red[256];
        int row = blk;
        const float* r = h1 + (long)row * DD;
        float x0 = r[t], x1 = r[t + 256];
        red[t] = x0 + x1; __syncthreads();
        for (int o = 128; o > 0; o >>= 1) { if (t < o) red[t] += red[t+o]; __syncthreads(); }
        float mean = red[0] * (1.0f/DD);
        __syncthreads();
        float d0 = x0 - mean, d1 = x1 - mean;
        red[t] = d0*d0 + d1*d1; __syncthreads();
        for (int o = 128; o > 0; o >>= 1) { if (t < o) red[t] += red[t+o]; __syncthreads(); }
        float inv = rsqrtf(red[0] * (1.0f/DD) + 1e-5f);
        __syncthreads();
        float y0 = d0 * inv * dn_g[t]     + dn_beta[t];
        float y1 = d1 * inv * dn_g[t+256] + dn_beta[t+256];
        y0 = 0.5f * y0 * (1.0f + erff(y0 * 0.70710678118654752f));
        y1 = 0.5f * y1 * (1.0f + erff(y1 * 0.70710678118654752f));
        red[t] = y0*w2[t] + y1*w2[t+256]; __syncthreads();
        for (int o = 128; o > 0; o >>= 1) { if (t < o) red[t] += red[t+o]; __syncthreads(); }
        if (t == 0) {
            float z = red[0] + b2[0];
            delta[row] = (z > 20.0f) ? z : log1pf(expf(z));
        }
    } else if (blk < 768) {
        __shared__ float red[256];
        int row = blk - 256;
        const float* r = proj_w + (long)row * 2560 + 512;
        red[t] = r[t]*aob[t] + r[t+256]*aob[t+256];
        __syncthreads();
        for (int o = 128; o > 0; o >>= 1) { if (t < o) red[t] += red[t+o]; __syncthreads(); }
        if (t == 0) pvec[row] = proj_b[row] + red[0];
    } else {
        int idx = (blk - 768) * 256 + t;
        int s = idx / (BB*DD);
        int r = idx - s * (BB*DD);
        int b = r >> 9;
        int d = r & 511;
        long gbase = ((long)s * BB + b) * 2048;
        const float* a = gA + gbase;
        const float* h = gB + gbase;
        const float* bi = bih + s*2048;
        const float* bh = bhh + s*2048;
        float ip = a[d]      + h[d]      + bi[d]      + bh[d];
        float fp = a[512+d]  + h[512+d]  + bi[512+d]  + bh[512+d];
        float gp = a[1024+d] + h[1024+d] + bi[1024+d] + bh[1024+d];
        float op = a[1536+d] + h[1536+d] + bi[1536+d] + bh[1536+d];
        float i_g = sigf(ip);
        float f_g = sigf(fp);
        float g_g = tanhf(gp);
        float o_g = sigf(op);
        float c   = lstm_c[idx];
        float craw = f_g * c + i_g * g_g;
        float hn   = o_g * tanhf(craw);
        float dec  = decays[s];
        h_new[idx] = hn;
        c_new[idx] = dec * c + (1.0f - dec) * craw;
        bf16 hh = __float2bfloat16_rn(hn);
        hnh[idx] = hh;
        hnl[idx] = __float2bfloat16_rn(hn - __bfloat162float(hh));
    }
}

// ========================= persistent chain kernel ===========================
// 256 blocks. Each iter: split-K-2 GEMM (256 tile-jobs) -> barrier ->
// epilogue (2 owned elts/thread, sums 2 planes) -> barrier. y in registers.
__global__ void __launch_bounds__(256, 2)
chain_kernel(const bf16* __restrict__ hph, const bf16* __restrict__ hpl,
             const bf16* __restrict__ wpowh, const bf16* __restrict__ wpowl,
             float* __restrict__ U,
             bf16* __restrict__ th, bf16* __restrict__ tl,
             const float* __restrict__ delta,
             const float* __restrict__ h_prev,
             const float* __restrict__ bx,
             float* __restrict__ out_hssm,
             bf16* __restrict__ hsh, bf16* __restrict__ hsl)
{
    extern __shared__ char smem[];
    const int tid = threadIdx.x;
    const long PU = (long)BB * 8 * DD;
    const long idx0 = ((long)blockIdx.x * 256 + tid) * 2;
    const int row = (int)(idx0 >> 9);
    const int col = (int)(idx0 & 511);
    const float dval = delta[row];

    float y[2];
    y[0] = h_prev[idx0];
    y[1] = h_prev[idx0 + 1];

    for (int iter = 0; iter < 2; iter++) {
        {
            int kz   = blockIdx.x >> 7;       // 0..1
            int tile = blockIdx.x & 127;
            GTask T = {};
            T.Xhi = iter ? th : hph;  T.Xlo = iter ? tl : hpl;  T.ldX = DD;
            T.Whi = wpowh;            T.Wlo = wpowl;            T.ldW = DD;
            T.C = U + (long)kz * PU;  T.ldC = 8*DD;
            T.K = 256; T.kofs = kz*256; T.nsplit = NOSPLIT; T.mtiles = 2;
            gemm_tile(T, tile, smem);
        }
        grid_barrier(&g_gen1, &g_cnt1, 256);

        const int k0 = iter * 8;
        const float* u0 = U + (long)row * 4096 + col;
        float c = 1.0f, tlast[2] = {0.0f, 0.0f};
        for (int j = 0; j < 8; j++) {
            c *= dval / (float)(k0 + j + 1);
            #pragma unroll
            for (int e = 0; e < 2; e++) {
                float u = u0[j*512 + e] + u0[PU + j*512 + e];
                float term = c * u;
                tlast[e] = term;
                y[e] += term;
            }
        }
        if (iter == 0) {
            #pragma unroll
            for (int e = 0; e < 2; e++) {
                bf16 h = __float2bfloat16_rn(tlast[e]);
                th[idx0 + e] = h;
                tl[idx0 + e] = __float2bfloat16_rn(tlast[e] - __bfloat162float(h));
            }
            grid_barrier(&g_gen1, &g_cnt1, 256);
        } else {
            #pragma unroll
            for (int e = 0; e < 2; e++) {
                float yy = y[e] + dval * bx[idx0 + e];
                out_hssm[idx0 + e] = yy;
                bf16 h = __float2bfloat16_rn(yy);
                hsh[idx0 + e] = h;
                hsl[idx0 + e] = __float2bfloat16_rn(yy - __bfloat162float(h));
            }
        }
    }
}

// ========================= persistent tail kernel ============================
// 256 blocks: [q splitK4 + hssm-proj splitK4 : 128 busy] -> barrier -> attn ->
// barrier -> [ctx@M splitK4 : 64 busy] -> barrier -> proj reduce(14) + LN.
__global__ void __launch_bounds__(256, 2)
tail_kernel(const bf16* __restrict__ hsh, const bf16* __restrict__ hsl,
            const bf16* __restrict__ aiwh, const bf16* __restrict__ aiwl,
            const bf16* __restrict__ pwh, const bf16* __restrict__ pwl,
            const bf16* __restrict__ mh, const bf16* __restrict__ ml,
            float* __restrict__ qp, float* __restrict__ kvp,
            float* __restrict__ part,
            const float* __restrict__ attn_in_b,
            bf16* __restrict__ cxh, bf16* __restrict__ cxl,
            const float* __restrict__ pvec,
            const float* __restrict__ pg, const float* __restrict__ pbe,
            float* __restrict__ out_y)
{
    extern __shared__ char smem[];
    const int tid = threadIdx.x;
    const int blk = blockIdx.x;

    // ---- phase A: q splitK4 (64 blk) + hssm-proj splitK4 (64 blk) ----
    if (blk < 128) {
        GTask T = {};
        T.ldX = DD; T.nsplit = NOSPLIT; T.mtiles = 2; T.K = 128;
        T.Xhi = hsh; T.Xlo = hsl;
        if (blk < 64) {
            int kz = blk >> 4;
            T.Whi = aiwh; T.Wlo = aiwl; T.ldW = DD;
            T.C = qp + (long)kz*BB*DD; T.ldC = DD; T.kofs = kz*128;
            gemm_tile(T, blk & 15, smem);
        } else {
            int b2 = blk - 64;
            int kz = b2 >> 4;
            T.Whi = pwh; T.Wlo = pwl; T.ldW = 5*DD;
            T.C = part + (long)kz*BB*DD; T.ldC = DD; T.kofs = kz*128;
            gemm_tile(T, b2 & 15, smem);
        }
    }
    grid_barrier(&g_gen2, &g_cnt2, 256);

    // ---- phase B: attention (block = batch) ----
    {
        int b    = blk;
        int warp = tid >> 5;
        int lane = tid & 31;
        const long QP = (long)BB*DD;
        const long KP = (long)SS*BB*2*DD;

        long qo = (long)b * DD + warp * 64;
        float q0 = attn_in_b[warp*64 + lane];
        float q1 = attn_in_b[warp*64 + lane + 32];
        #pragma unroll
        for (int p = 0; p < 4; p++) {
            q0 += qp[p*QP + qo + lane];
            q1 += qp[p*QP + qo + lane + 32];
        }

        float sc[SS];
        #pragma unroll
        for (int s = 0; s < SS; s++) {
            long ko = (long)(s*BB + b) * 1024 + warp * 64;
            float k0 = kvp[ko + lane]      + kvp[KP + ko + lane]
                     + attn_in_b[512 + warp*64 + lane];
            float k1 = kvp[ko + lane + 32] + kvp[KP + ko + lane + 32]
                     + attn_in_b[512 + warp*64 + lane + 32];
            float d = q0 * k0 + q1 * k1;
            #pragma unroll
            for (int o = 16; o > 0; o >>= 1) d += __shfl_xor_sync(0xffffffff, d, o);
            sc[s] = d * 0.125f;
        }
        float m = fmaxf(sc[0], fmaxf(sc[1], sc[2]));
        float e[SS], sum = 0.0f;
        #pragma unroll
        for (int s = 0; s < SS; s++) { e[s] = expf(sc[s] - m); sum += e[s]; }
        float inv = 1.0f / sum;

        float c0 = 0.0f, c1 = 0.0f;
        #pragma unroll
        for (int s = 0; s < SS; s++) {
            long vo = (long)(s*BB + b) * 1024 + 512 + warp * 64;
            float v0 = kvp[vo + lane]      + kvp[KP + vo + lane]
                     + attn_in_b[1024 + warp*64 + lane];
            float v1 = kvp[vo + lane + 32] + kvp[KP + vo + lane + 32]
                     + attn_in_b[1024 + warp*64 + lane + 32];
            float w = e[s] * inv;
            c0 += w * v0;
            c1 += w * v1;
        }
        long o0 = (long)b * DD + warp*64 + lane;
        bf16 h0 = __float2bfloat16_rn(c0);
        bf16 h1 = __float2bfloat16_rn(c1);
        cxh[o0]      = h0;
        cxl[o0]      = __float2bfloat16_rn(c0 - __bfloat162float(h0));
        cxh[o0 + 32] = h1;
        cxl[o0 + 32] = __float2bfloat16_rn(c1 - __bfloat162float(h1));
    }
    grid_barrier(&g_gen2, &g_cnt2, 256);

    // ---- phase C: ctx @ M splitK4 (64 blk) -> part planes 4..7 ----
    if (blk < 64) {
        int kz = blk >> 4;
        GTask T = {};
        T.Xhi = cxh; T.Xlo = cxl; T.ldX = DD;
        T.Whi = mh; T.Wlo = ml; T.ldW = DD;
        T.C = part + (long)(4+kz)*BB*DD; T.ldC = DD;
        T.K = 128; T.kofs = kz*128; T.nsplit = NOSPLIT; T.mtiles = 2;
        gemm_tile(T, blk & 15, smem);
    }
    grid_barrier(&g_gen2, &g_cnt2, 256);

    // ---- phase D: proj reduce (14 planes) + LN ----
    {
        float* red = (float*)smem;
        int row = blk, t = tid;
        long o0 = (long)row*DD + t, o1 = o0 + 256;
        const long PL = (long)BB*DD;
        float x0 = pvec[t], x1 = pvec[t+256];
        #pragma unroll
        for (int p = 0; p < 14; p++) { x0 += part[p*PL + o0]; x1 += part[p*PL + o1]; }

        red[t] = x0 + x1; __syncthreads();
        for (int o = 128; o > 0; o >>= 1) { if (t < o) red[t] += red[t+o]; __syncthreads(); }
        float mean = red[0] * (1.0f/DD);
        __syncthreads();

        float d0 = x0 - mean, d1 = x1 - mean;
        red[t] = d0*d0 + d1*d1; __syncthreads();
        for (int o = 128; o > 0; o >>= 1) { if (t < o) red[t] += red[t+o]; __syncthreads(); }
        float inv = rsqrtf(red[0] * (1.0f/DD) + 1e-5f);

        out_y[o0] = d0 * inv * pg[t]     + pbe[t];
        out_y[o1] = d1 * inv * pg[t+256] + pbe[t+256];
    }
}

// ---------------------------------------------------------------------------
static inline GTask mk_task(const bf16* Xhi, const bf16* Xlo, int ldX,
                            const bf16* Whi, const bf16* Wlo, int ldW,
                            float* C, int ldC, int K, int kofs,
                            int mtiles, int ntiles)
{
    GTask t = {};
    t.Xhi = Xhi; t.Xlo = Xlo; t.ldX = ldX;
    t.Whi = Whi; t.Wlo = Wlo; t.ldW = ldW;
    t.C = C; t.ldC = ldC;
    t.K = K; t.kofs = kofs; t.nsplit = NOSPLIT;
    t.mtiles = mtiles; t.blocks = mtiles*ntiles;
    return t;
}

extern "C" void kernel_launch(void* const* d_in, const int* in_sizes, int n_in,
                              void* d_out, int out_size)
{
    (void)in_sizes; (void)n_in; (void)out_size;

    const float* x        = (const float*)d_in[0];
    const float* h_prev   = (const float*)d_in[1];
    const float* lstm_h   = (const float*)d_in[2];
    const float* lstm_c   = (const float*)d_in[3];
    const float* A        = (const float*)d_in[4];
    const float* Bm       = (const float*)d_in[5];
    const float* dn_w1    = (const float*)d_in[6];
    const float* dn_b1    = (const float*)d_in[7];
    const float* dn_g     = (const float*)d_in[8];
    const float* dn_beta  = (const float*)d_in[9];
    const float* dn_w2    = (const float*)d_in[10];
    const float* dn_b2    = (const float*)d_in[11];
    const float* lstm_wih = (const float*)d_in[12];
    const float* lstm_whh = (const float*)d_in[13];
    const float* lstm_bih = (const float*)d_in[14];
    const float* lstm_bhh = (const float*)d_in[15];
    const float* decays   = (const float*)d_in[16];
    const float* attn_in_w  = (const float*)d_in[17];
    const float* attn_in_b  = (const float*)d_in[18];
    const float* attn_out_w = (const float*)d_in[19];
    const float* attn_out_b = (const float*)d_in[20];
    const float* proj_w   = (const float*)d_in[21];
    const float* proj_b   = (const float*)d_in[22];
    const float* proj_g   = (const float*)d_in[23];
    const float* proj_beta= (const float*)d_in[24];

    float* out = (float*)d_out;
    float* out_y    = out;
    float* out_hssm = out + BB*DD;
    float* out_hnew = out + 2*BB*DD;
    float* out_cnew = out + 2*BB*DD + SS*BB*DD;

    float *p_h1, *p_delta, *p_bx, *p_U, *p_gA, *p_gB, *p_kvp, *p_qp, *p_part, *p_pvec;
    cudaGetSymbolAddress((void**)&p_h1,    g_h1);
    cudaGetSymbolAddress((void**)&p_delta, g_delta);
    cudaGetSymbolAddress((void**)&p_bx,    g_bx);
    cudaGetSymbolAddress((void**)&p_U,     g_U);
    cudaGetSymbolAddress((void**)&p_gA,    g_gA);
    cudaGetSymbolAddress((void**)&p_gB,    g_gB);
    cudaGetSymbolAddress((void**)&p_kvp,   g_kvp);
    cudaGetSymbolAddress((void**)&p_qp,    g_qp);
    cudaGetSymbolAddress((void**)&p_part,  g_part);
    cudaGetSymbolAddress((void**)&p_pvec,  g_pvec);

    bf16 *xh,*xl,*hph,*hpl,*lhh,*lhl,*w1h,*w1l,*bmh,*bml,*wihh,*wihl,*whhh,*whhl,
         *aiwh,*aiwl,*pwh,*pwl,*wpowh,*wpowl,*ath,*atl,*a2th,*a2tl,*a4th,*a4tl,
         *aoth,*aotl,*mh,*ml,*th,*tl,*hsh,*hsl,*hnh,*hnl,*cxh,*cxl;
    cudaGetSymbolAddress((void**)&xh, g_xh);     cudaGetSymbolAddress((void**)&xl, g_xl);
    cudaGetSymbolAddress((void**)&hph, g_hph);   cudaGetSymbolAddress((void**)&hpl, g_hpl);
    cudaGetSymbolAddress((void**)&lhh, g_lhh);   cudaGetSymbolAddress((void**)&lhl, g_lhl);
    cudaGetSymbolAddress((void**)&w1h, g_w1h);   cudaGetSymbolAddress((void**)&w1l, g_w1l);
    cudaGetSymbolAddress((void**)&bmh, g_bmh);   cudaGetSymbolAddress((void**)&bml, g_bml);
    cudaGetSymbolAddress((void**)&wihh, g_wihh); cudaGetSymbolAddress((void**)&wihl, g_wihl);
    cudaGetSymbolAddress((void**)&whhh, g_whhh); cudaGetSymbolAddress((void**)&whhl, g_whhl);
    cudaGetSymbolAddress((void**)&aiwh, g_aiwh); cudaGetSymbolAddress((void**)&aiwl, g_aiwl);
    cudaGetSymbolAddress((void**)&pwh, g_pwh);   cudaGetSymbolAddress((void**)&pwl, g_pwl);
    cudaGetSymbolAddress((void**)&wpowh, g_wpowh); cudaGetSymbolAddress((void**)&wpowl, g_wpowl);
    cudaGetSymbolAddress((void**)&ath, g_ath);   cudaGetSymbolAddress((void**)&atl, g_atl);
    cudaGetSymbolAddress((void**)&a2th, g_a2th); cudaGetSymbolAddress((void**)&a2tl, g_a2tl);
    cudaGetSymbolAddress((void**)&a4th, g_a4th); cudaGetSymbolAddress((void**)&a4tl, g_a4tl);
    cudaGetSymbolAddress((void**)&aoth, g_aoth); cudaGetSymbolAddress((void**)&aotl, g_aotl);
    cudaGetSymbolAddress((void**)&mh, g_mh);     cudaGetSymbolAddress((void**)&ml, g_ml);
    cudaGetSymbolAddress((void**)&th, g_th);     cudaGetSymbolAddress((void**)&tl, g_tl);
    cudaGetSymbolAddress((void**)&hsh, g_hsh);   cudaGetSymbolAddress((void**)&hsl, g_hsl);
    cudaGetSymbolAddress((void**)&hnh, g_hnh);   cudaGetSymbolAddress((void**)&hnl, g_hnl);
    cudaGetSymbolAddress((void**)&cxh, g_cxh);   cudaGetSymbolAddress((void**)&cxl, g_cxl);

    cudaFuncSetAttribute(gemm_mma,
        cudaFuncAttributeMaxDynamicSharedMemorySize, SMEM_SZ);
    cudaFuncSetAttribute(chain_kernel,
        cudaFuncAttributeMaxDynamicSharedMemorySize, SMEM_SZ);
    cudaFuncSetAttribute(tail_kernel,
        cudaFuncAttributeMaxDynamicSharedMemorySize, SMEM_SZ);

    const long W2 = (long)DD*DD;
    const long KP = (long)SS*BB*2*DD;

    // ---- K1: split all operands + transposes ----
    {
        STaskSet st = {};
        auto add = [&](int i, const float* s, bf16* h, bf16* l, long n) {
            st.t[i] = { s, h, l, (int)(n / 2048) };
        };
        add(0, x,        xh,   xl,   (long)BB*DD);
        add(1, h_prev,   hph,  hpl,  (long)BB*DD);
        add(2, lstm_h,   lhh,  lhl,  (long)SS*BB*DD);
        add(3, dn_w1,    w1h,  w1l,  W2);
        add(4, Bm,       bmh,  bml,  W2);
        add(5, lstm_wih, wihh, wihl, (long)SS*4*W2);
        add(6, lstm_whh, whhh, whhl, (long)SS*4*W2);
        add(7, attn_in_w, aiwh, aiwl, 3*W2);
        add(8, proj_w,   pwh,  pwl,  5*W2);
        add(9, A,        wpowh, wpowl, W2);
        st.ntasks = 10;
        int total = 0;
        for (int i = 0; i < 10; i++) total += st.t[i].blocks;
        prep_kernel<<<total + 512, 256>>>(st, total,
            A, ath, atl, attn_out_w, aoth, aotl);
    }

    // ---- K2 (G1, 480 blocks): h1|bx, 6 lstm partials, A^2 (+A2T), M ----
    {
        GTaskSet ts = {};
        GTask t0 = mk_task(xh, xl, DD, w1h, w1l, DD, p_h1, DD, DD, 0, 2, 16);
        t0.bias = dn_b1; t0.Wn2hi = bmh; t0.Wn2lo = bml;
        t0.Cn2 = p_bx; t0.ldCn2 = DD; t0.nsplit = DD;
        ts.t[0] = t0;
        for (int s = 0; s < SS; s++) {
            ts.t[1+s] = mk_task(xh, xl, DD, wihh + (long)s*4*W2, wihl + (long)s*4*W2, DD,
                                p_gA + (long)s*BB*4*DD, 4*DD, DD, 0, 2, 32);
            ts.t[4+s] = mk_task(lhh + (long)s*BB*DD, lhl + (long)s*BB*DD, DD,
                                whhh + (long)s*4*W2, whhl + (long)s*4*W2, DD,
                                p_gB + (long)s*BB*4*DD, 4*DD, DD, 0, 2, 32);
        }
        GTask ta = mk_task(wpowh, wpowl, DD, ath, atl, DD, nullptr, DD, DD, 0, 4, 8);
        ta.Chi = wpowh + W2; ta.Clo = wpowl + W2;
        ta.Cthi = a2th; ta.Ctlo = a2tl; ta.ldCt = DD;
        ts.t[7] = ta;
        GTask tm = mk_task(pwh + 512, pwl + 512, 5*DD, aoth, aotl, DD,
                           nullptr, DD, DD, 0, 4, 8);
        tm.Chi = mh; tm.Clo = ml;
        ts.t[8] = tm;
        ts.ntasks = 9;
        gemm_mma<<<480, 256, SMEM_SZ>>>(ts);
    }

    // ---- K3: S1 fused ----
    s1_kernel<<<2304, 256>>>(p_h1, dn_g, dn_beta, dn_w2, dn_b2, p_delta,
                             proj_w, attn_out_b, proj_b, p_pvec,
                             p_gA, p_gB, lstm_bih, lstm_bhh, lstm_c, decays,
                             out_hnew, out_cnew, hnh, hnl);

    // ---- K4 (G2, 256 blocks): A^3, A^4 (+A4T), kv split-K-2 ----
    {
        GTaskSet ts = {};
        GTask t3 = mk_task(wpowh + W2, wpowl + W2, DD, ath, atl, DD,
                           nullptr, DD, DD, 0, 4, 8);
        t3.Chi = wpowh + 2*W2; t3.Clo = wpowl + 2*W2;
        ts.t[0] = t3;
        GTask t4 = mk_task(wpowh + W2, wpowl + W2, DD, a2th, a2tl, DD,
                           nullptr, DD, DD, 0, 4, 8);
        t4.Chi = wpowh + 3*W2; t4.Clo = wpowl + 3*W2;
        t4.Cthi = a4th; t4.Ctlo = a4tl; t4.ldCt = DD;
        ts.t[1] = t4;
        for (int kz = 0; kz < 2; kz++)
            ts.t[2+kz] = mk_task(hnh, hnl, DD, aiwh + W2, aiwl + W2, DD,
                                 p_kvp + (long)kz*KP, 2*DD, 256, kz*256, 6, 16);
        ts.ntasks = 4;
        gemm_mma<<<256, 256, SMEM_SZ>>>(ts);
    }

    // ---- K5 (G3, 224 blocks): A^5..A^8, h_new proj partials (planes 8..13) ----
    {
        GTaskSet ts = {};
        GTask t5 = mk_task(wpowh + 3*W2, wpowl + 3*W2, DD, ath, atl, DD,
                           nullptr, DD, DD, 0, 4, 8);
        t5.Chi = wpowh + 4*W2; t5.Clo = wpowl + 4*W2;
        ts.t[0] = t5;
        GTask t6 = mk_task(wpowh + 3*W2, wpowl + 3*W2, DD, a2th, a2tl, DD,
                           nullptr, DD, DD, 0, 4, 8);
        t6.Chi = wpowh + 5*W2; t6.Clo = wpowl + 5*W2;
        ts.t[1] = t6;
        GTask t7 = mk_task(wpowh + 2*W2, wpowl + 2*W2, DD, a4th, a4tl, DD,
                           nullptr, DD, DD, 0, 4, 8);
        t7.Chi = wpowh + 6*W2; t7.Clo = wpowl + 6*W2;
        ts.t[2] = t7;
        GTask t8 = mk_task(wpowh + 3*W2, wpowl + 3*W2, DD, a4th, a4tl, DD,
                           nullptr, DD, DD, 0, 4, 8);
        t8.Chi = wpowh + 7*W2; t8.Clo = wpowl + 7*W2;
        ts.t[3] = t8;
        int p = 0;
        for (int i = 0; i < SS; i++)
            for (int kz = 0; kz < 2; kz++, p++)
                ts.t[4+p] = mk_task(hnh + (long)i*BB*DD, hnl + (long)i*BB*DD, DD,
                                    pwh + 1024 + i*512, pwl + 1024 + i*512, 5*DD,
                                    p_part + (long)(8 + p)*BB*DD, DD,
                                    256, kz*256, 2, 8);
        ts.ntasks = 10;
        gemm_mma<<<224, 256, SMEM_SZ>>>(ts);
    }

    // ---- K6: persistent chain (split-K-2, 256 blocks) ----
    chain_kernel<<<256, 256, SMEM_SZ>>>(hph, hpl, wpowh, wpowl, p_U, th, tl,
                                        p_delta, h_prev, p_bx,
                                        out_hssm, hsh, hsl);

    // ---- K7: persistent tail ----
    tail_kernel<<<256, 256, SMEM_SZ>>>(hsh, hsl, aiwh, aiwl, pwh, pwl, mh, ml,
                                       p_qp, p_kvp, p_part, attn_in_b,
                                       cxh, cxl, p_pvec, proj_g, proj_beta,
                                       out_y);
}